// round 1
// baseline (speedup 1.0000x reference)
#include <cuda_runtime.h>
#include <math.h>

#define N_TOK  8192
#define IN_DIM 1024
#define D_HEAD 128
#define BM 64
#define BN 64

// Scratch for Q, K, V projections (4 MB each) — allocation-free rule.
__device__ float g_q[N_TOK * D_HEAD];
__device__ float g_k[N_TOK * D_HEAD];
__device__ float g_v[N_TOK * D_HEAD];

// ---------------------------------------------------------------------------
// Kernel 1: QKV projection.  out = z @ W + b  for W in {Wq, Wk, Wv}.
// Block computes a 128x128 output tile; 256 threads, 8x8 register tile each.
// ---------------------------------------------------------------------------
__global__ __launch_bounds__(256) void qkv_kernel(
    const float* __restrict__ z,
    const float* __restrict__ Wq, const float* __restrict__ bq,
    const float* __restrict__ Wk, const float* __restrict__ bk,
    const float* __restrict__ Wv, const float* __restrict__ bv)
{
    const float* W; const float* b; float* out;
    if (blockIdx.y == 0)      { W = Wq; b = bq; out = g_q; }
    else if (blockIdx.y == 1) { W = Wk; b = bk; out = g_k; }
    else                      { W = Wv; b = bv; out = g_v; }

    __shared__ float sZ[128][32];
    __shared__ float sW[32][128];

    const int tid = threadIdx.x;
    const int ty  = tid >> 4;    // 0..15
    const int tx  = tid & 15;    // 0..15
    const int row0 = blockIdx.x * 128;

    float acc[8][8];
    #pragma unroll
    for (int i = 0; i < 8; i++)
        #pragma unroll
        for (int j = 0; j < 8; j++) acc[i][j] = 0.f;

    for (int k0 = 0; k0 < IN_DIM; k0 += 32) {
        // Load z tile: 128 rows x 32 cols
        {
            int r  = tid >> 3;             // 0..31
            int c4 = (tid & 7) << 2;       // 0..28
            #pragma unroll
            for (int p = 0; p < 4; p++) {
                float4 v4 = *(const float4*)&z[(size_t)(row0 + r + p * 32) * IN_DIM + k0 + c4];
                *(float4*)&sZ[r + p * 32][c4] = v4;
            }
        }
        // Load W tile: 32 rows x 128 cols
        {
            int kk = tid >> 5;             // 0..7
            int cw = (tid & 31) << 2;      // 0..124
            #pragma unroll
            for (int p = 0; p < 4; p++) {
                float4 w4 = *(const float4*)&W[(size_t)(k0 + kk + p * 8) * D_HEAD + cw];
                *(float4*)&sW[kk + p * 8][cw] = w4;
            }
        }
        __syncthreads();

        #pragma unroll
        for (int kk = 0; kk < 32; kk++) {
            float a[8], bb[8];
            #pragma unroll
            for (int i = 0; i < 8; i++) a[i] = sZ[ty + 16 * i][kk];
            #pragma unroll
            for (int j = 0; j < 8; j++) bb[j] = sW[kk][tx + 16 * j];
            #pragma unroll
            for (int i = 0; i < 8; i++)
                #pragma unroll
                for (int j = 0; j < 8; j++)
                    acc[i][j] = fmaf(a[i], bb[j], acc[i][j]);
        }
        __syncthreads();
    }

    #pragma unroll
    for (int j = 0; j < 8; j++) {
        float bias = b[tx + 16 * j];
        #pragma unroll
        for (int i = 0; i < 8; i++) {
            out[(size_t)(row0 + ty + 16 * i) * D_HEAD + tx + 16 * j] = acc[i][j] + bias;
        }
    }
}

// ---------------------------------------------------------------------------
// Kernel 2: fused flash attention.  64 query rows per CTA, 64-wide key tiles,
// online softmax; K held transposed in SMEM (ld = 65) for conflict-free S GEMM.
// ---------------------------------------------------------------------------
#define SMEM_Q   (BM * D_HEAD)          // 8192 floats
#define SMEM_KT  (D_HEAD * 65)          // 8320
#define SMEM_V   (BN * D_HEAD)          // 8192
#define SMEM_S   (BM * 65)              // 4160
#define ATTN_SMEM_FLOATS (SMEM_Q + SMEM_KT + SMEM_V + SMEM_S + 3 * BM + 4 * BM)
#define ATTN_SMEM_BYTES  (ATTN_SMEM_FLOATS * 4)

__global__ __launch_bounds__(256) void attn_kernel(float* __restrict__ out)
{
    extern __shared__ float smem[];
    float* sQ     = smem;                 // [64][128]
    float* sKT    = sQ  + SMEM_Q;         // [128][65]  (d-major, padded)
    float* sV     = sKT + SMEM_KT;        // [64][128]
    float* sS     = sV  + SMEM_V;         // [64][65]
    float* sM     = sS  + SMEM_S;         // [64]
    float* sL     = sM  + BM;             // [64]
    float* sAlpha = sL  + BM;             // [64]
    float* sRed   = sAlpha + BM;          // [4][64]

    const float scale = 0.08838834764831845f;   // 1/sqrt(128)
    const int tid = threadIdx.x;
    const int ty  = tid >> 4;     // 0..15
    const int tx  = tid & 15;     // 0..15
    const int q0  = blockIdx.x * BM;

    // Load and pre-scale Q tile.
    {
        int r = tid >> 5;             // 0..7
        int c = (tid & 31) << 2;      // 0..124
        #pragma unroll
        for (int p = 0; p < 8; p++) {
            float4 v = *(const float4*)&g_q[(size_t)(q0 + r + p * 8) * D_HEAD + c];
            v.x *= scale; v.y *= scale; v.z *= scale; v.w *= scale;
            *(float4*)&sQ[(r + p * 8) * D_HEAD + c] = v;
        }
    }
    if (tid < BM) { sM[tid] = -INFINITY; sL[tid] = 0.f; }

    float o[4][8];
    #pragma unroll
    for (int i = 0; i < 4; i++)
        #pragma unroll
        for (int j = 0; j < 8; j++) o[i][j] = 0.f;

    __syncthreads();

    const int row = tid >> 2;     // 0..63  (softmax row ownership)
    const int qq  = tid & 3;      // 0..3   (16-col quarter)

    for (int k0 = 0; k0 < N_TOK; k0 += BN) {
        // Load K (transposed into sKT) and V tiles.
        {
            int key = tid >> 5;           // 0..7
            int c   = (tid & 31) << 2;    // 0..124
            #pragma unroll
            for (int p = 0; p < 8; p++) {
                int kr = key + p * 8;
                float4 kv = *(const float4*)&g_k[(size_t)(k0 + kr) * D_HEAD + c];
                sKT[(c + 0) * 65 + kr] = kv.x;
                sKT[(c + 1) * 65 + kr] = kv.y;
                sKT[(c + 2) * 65 + kr] = kv.z;
                sKT[(c + 3) * 65 + kr] = kv.w;
                float4 vv = *(const float4*)&g_v[(size_t)(k0 + kr) * D_HEAD + c];
                *(float4*)&sV[kr * D_HEAD + c] = vv;
            }
        }
        __syncthreads();

        // S = (scaled Q) @ K^T : each thread owns 4x4 of the 64x64 tile.
        float s[4][4];
        #pragma unroll
        for (int i = 0; i < 4; i++)
            #pragma unroll
            for (int j = 0; j < 4; j++) s[i][j] = 0.f;

        #pragma unroll 8
        for (int kk = 0; kk < D_HEAD; kk++) {
            float a[4], bk_[4];
            #pragma unroll
            for (int i = 0; i < 4; i++) a[i] = sQ[(ty + 16 * i) * D_HEAD + kk];
            #pragma unroll
            for (int j = 0; j < 4; j++) bk_[j] = sKT[kk * 65 + tx + 16 * j];
            #pragma unroll
            for (int i = 0; i < 4; i++)
                #pragma unroll
                for (int j = 0; j < 4; j++)
                    s[i][j] = fmaf(a[i], bk_[j], s[i][j]);
        }
        #pragma unroll
        for (int i = 0; i < 4; i++)
            #pragma unroll
            for (int j = 0; j < 4; j++)
                sS[(ty + 16 * i) * 65 + tx + 16 * j] = s[i][j];
        __syncthreads();

        // Row max (partial per 16-col quarter, then combine).
        const int base = row * 65 + qq * 16;
        float pm = -INFINITY;
        #pragma unroll
        for (int cc = 0; cc < 16; cc++) pm = fmaxf(pm, sS[base + cc]);
        sRed[qq * 64 + row] = pm;
        __syncthreads();

        if (tid < BM) {
            float mt = fmaxf(fmaxf(sRed[tid], sRed[64 + tid]),
                             fmaxf(sRed[128 + tid], sRed[192 + tid]));
            float mold = sM[tid];
            float mnew = fmaxf(mold, mt);
            sM[tid]     = mnew;
            sAlpha[tid] = __expf(mold - mnew);   // 0 on first tile (mold = -inf)
        }
        __syncthreads();

        // exp pass + row-sum partials; overwrite sS with P.
        float mnew = sM[row];
        float psum = 0.f;
        #pragma unroll
        for (int cc = 0; cc < 16; cc++) {
            float p = __expf(sS[base + cc] - mnew);
            sS[base + cc] = p;
            psum += p;
        }
        sRed[qq * 64 + row] = psum;
        __syncthreads();

        if (tid < BM) {
            sL[tid] = sL[tid] * sAlpha[tid] +
                      (sRed[tid] + sRed[64 + tid] + sRed[128 + tid] + sRed[192 + tid]);
        }

        // Rescale running output by alpha (per-row).
        float al[4];
        #pragma unroll
        for (int i = 0; i < 4; i++) al[i] = sAlpha[ty + 16 * i];
        #pragma unroll
        for (int i = 0; i < 4; i++)
            #pragma unroll
            for (int j = 0; j < 8; j++) o[i][j] *= al[i];

        // O += P @ V
        #pragma unroll 4
        for (int kk = 0; kk < BN; kk++) {
            float p[4], v[8];
            #pragma unroll
            for (int i = 0; i < 4; i++) p[i] = sS[(ty + 16 * i) * 65 + kk];
            #pragma unroll
            for (int j = 0; j < 8; j++) v[j] = sV[kk * D_HEAD + tx + 16 * j];
            #pragma unroll
            for (int i = 0; i < 4; i++)
                #pragma unroll
                for (int j = 0; j < 8; j++)
                    o[i][j] = fmaf(p[i], v[j], o[i][j]);
        }
        __syncthreads();
    }

    // Epilogue: divide by l and store.
    float linv[4];
    #pragma unroll
    for (int i = 0; i < 4; i++) linv[i] = 1.f / sL[ty + 16 * i];
    #pragma unroll
    for (int i = 0; i < 4; i++)
        #pragma unroll
        for (int j = 0; j < 8; j++)
            out[(size_t)(q0 + ty + 16 * i) * D_HEAD + tx + 16 * j] = o[i][j] * linv[i];
}

// ---------------------------------------------------------------------------
extern "C" void kernel_launch(void* const* d_in, const int* in_sizes, int n_in,
                              void* d_out, int out_size)
{
    const float* z  = (const float*)d_in[0];
    const float* Wq = (const float*)d_in[1];
    const float* bq = (const float*)d_in[2];
    const float* Wk = (const float*)d_in[3];
    const float* bk = (const float*)d_in[4];
    const float* Wv = (const float*)d_in[5];
    const float* bv = (const float*)d_in[6];
    float* out = (float*)d_out;

    // Idempotent; not a stream op, so safe under graph capture.
    cudaFuncSetAttribute(attn_kernel, cudaFuncAttributeMaxDynamicSharedMemorySize,
                         ATTN_SMEM_BYTES);

    dim3 gqkv(N_TOK / 128, 3);
    qkv_kernel<<<gqkv, 256>>>(z, Wq, bq, Wk, bk, Wv, bv);

    attn_kernel<<<N_TOK / BM, 256, ATTN_SMEM_BYTES>>>(out);
}

// round 2
// speedup vs baseline: 1.9555x; 1.9555x over previous
#include <cuda_runtime.h>
#include <math.h>
#include <stdint.h>

#define N_TOK  8192
#define IN_DIM 1024
#define D_HEAD 128
#define BM 64
#define BN 64
#define LDQ 132            // padded row pitch (floats) for Q/K/V tiles
#define LDS_S 68           // padded pitch for S/P tile

// Scratch for Q, K, V projections (tf32-rounded fp32) — allocation-free rule.
__device__ float g_q[N_TOK * D_HEAD];
__device__ float g_k[N_TOK * D_HEAD];
__device__ float g_v[N_TOK * D_HEAD];

__device__ __forceinline__ float tf32_rna(float x) {
    uint32_t u;
    asm("cvt.rna.tf32.f32 %0, %1;" : "=r"(u) : "f"(x));
    return __uint_as_float(u);
}
__device__ __forceinline__ uint32_t fu(float x) { return __float_as_uint(x); }

__device__ __forceinline__ void mma_tf32(float (&d)[4],
    uint32_t a0, uint32_t a1, uint32_t a2, uint32_t a3,
    uint32_t b0, uint32_t b1)
{
    asm volatile(
        "mma.sync.aligned.m16n8k8.row.col.f32.tf32.tf32.f32 "
        "{%0,%1,%2,%3}, {%4,%5,%6,%7}, {%8,%9}, {%0,%1,%2,%3};\n"
        : "+f"(d[0]), "+f"(d[1]), "+f"(d[2]), "+f"(d[3])
        : "r"(a0), "r"(a1), "r"(a2), "r"(a3), "r"(b0), "r"(b1));
}

__device__ __forceinline__ void cp_async16(void* sdst, const void* gsrc) {
    uint32_t s = (uint32_t)__cvta_generic_to_shared(sdst);
    asm volatile("cp.async.cg.shared.global [%0], [%1], 16;\n" :: "r"(s), "l"(gsrc));
}
#define CP_COMMIT() asm volatile("cp.async.commit_group;\n" ::: "memory")
#define CP_WAIT(n)  asm volatile("cp.async.wait_group %0;\n" :: "n"(n) : "memory")

// ---------------------------------------------------------------------------
// Kernel 1: QKV projection (fp32 SIMT).  out = tf32_round(z @ W + b).
// ---------------------------------------------------------------------------
__global__ __launch_bounds__(256) void qkv_kernel(
    const float* __restrict__ z,
    const float* __restrict__ Wq, const float* __restrict__ bq,
    const float* __restrict__ Wk, const float* __restrict__ bk,
    const float* __restrict__ Wv, const float* __restrict__ bv)
{
    const float* W; const float* b; float* out;
    if (blockIdx.y == 0)      { W = Wq; b = bq; out = g_q; }
    else if (blockIdx.y == 1) { W = Wk; b = bk; out = g_k; }
    else                      { W = Wv; b = bv; out = g_v; }

    __shared__ float sZ[128][32];
    __shared__ float sW[32][128];

    const int tid = threadIdx.x;
    const int ty  = tid >> 4;
    const int tx  = tid & 15;
    const int row0 = blockIdx.x * 128;

    float acc[8][8];
    #pragma unroll
    for (int i = 0; i < 8; i++)
        #pragma unroll
        for (int j = 0; j < 8; j++) acc[i][j] = 0.f;

    for (int k0 = 0; k0 < IN_DIM; k0 += 32) {
        {
            int r  = tid >> 3;
            int c4 = (tid & 7) << 2;
            #pragma unroll
            for (int p = 0; p < 4; p++) {
                float4 v4 = *(const float4*)&z[(size_t)(row0 + r + p * 32) * IN_DIM + k0 + c4];
                *(float4*)&sZ[r + p * 32][c4] = v4;
            }
        }
        {
            int kk = tid >> 5;
            int cw = (tid & 31) << 2;
            #pragma unroll
            for (int p = 0; p < 4; p++) {
                float4 w4 = *(const float4*)&W[(size_t)(k0 + kk + p * 8) * D_HEAD + cw];
                *(float4*)&sW[kk + p * 8][cw] = w4;
            }
        }
        __syncthreads();

        #pragma unroll
        for (int kk = 0; kk < 32; kk++) {
            float a[8], bb[8];
            #pragma unroll
            for (int i = 0; i < 8; i++) a[i] = sZ[ty + 16 * i][kk];
            #pragma unroll
            for (int j = 0; j < 8; j++) bb[j] = sW[kk][tx + 16 * j];
            #pragma unroll
            for (int i = 0; i < 8; i++)
                #pragma unroll
                for (int j = 0; j < 8; j++)
                    acc[i][j] = fmaf(a[i], bb[j], acc[i][j]);
        }
        __syncthreads();
    }

    #pragma unroll
    for (int j = 0; j < 8; j++) {
        float bias = b[tx + 16 * j];
        #pragma unroll
        for (int i = 0; i < 8; i++) {
            out[(size_t)(row0 + ty + 16 * i) * D_HEAD + tx + 16 * j] =
                tf32_rna(acc[i][j] + bias);
        }
    }
}

// ---------------------------------------------------------------------------
// Kernel 2: flash attention with mma.sync tf32.
// 64 queries / CTA, 64-key tiles, 8 warps = 4 row-groups x 2 col-halves,
// double-buffered cp.async K/V, softmax via smem (thread-per-row).
// ---------------------------------------------------------------------------
#define SMEM_Q  (BM * LDQ)              // 8448
#define SMEM_KV (BN * LDQ)              // 8448 per buffer
#define SMEM_S  (BM * LDS_S)            // 4352
#define ATTN_SMEM_FLOATS (SMEM_Q + 4 * SMEM_KV + SMEM_S + 7 * BM)
#define ATTN_SMEM_BYTES  (ATTN_SMEM_FLOATS * 4)

__global__ __launch_bounds__(256) void attn_kernel(float* __restrict__ out)
{
    extern __shared__ float smem[];
    float* sQ  = smem;                        // [64][132]
    float* sK0 = sQ  + SMEM_Q;                // [64][132] x2
    float* sV0 = sK0 + 2 * SMEM_KV;           // [64][132] x2
    float* sS  = sV0 + 2 * SMEM_KV;           // [64][68]
    float* sM     = sS + SMEM_S;              // [64]
    float* sL     = sM + BM;
    float* sAlpha = sL + BM;
    float* sRed   = sAlpha + BM;              // [4][64]

    const float scale = 0.08838834764831845f; // 1/sqrt(128)
    const int tid  = threadIdx.x;
    const int lane = tid & 31;
    const int wid  = tid >> 5;
    const int rg   = (wid & 3) * 16;          // row group base
    const int wc   = wid >> 2;                // 0,1 column half
    const int lq   = lane >> 2;               // 0..7
    const int lr   = lane & 3;                // 0..3
    const int q0   = blockIdx.x * BM;

    // Load + scale + tf32-round the Q tile.
    {
        int r = tid >> 5;
        int c = (tid & 31) << 2;
        #pragma unroll
        for (int p = 0; p < 8; p++) {
            float4 v = *(const float4*)&g_q[(size_t)(q0 + r + p * 8) * D_HEAD + c];
            v.x = tf32_rna(v.x * scale); v.y = tf32_rna(v.y * scale);
            v.z = tf32_rna(v.z * scale); v.w = tf32_rna(v.w * scale);
            *(float4*)&sQ[(r + p * 8) * LDQ + c] = v;
        }
    }
    if (tid < BM) { sM[tid] = -INFINITY; sL[tid] = 0.f; }

    float oacc[8][4];
    #pragma unroll
    for (int nb = 0; nb < 8; nb++)
        #pragma unroll
        for (int j = 0; j < 4; j++) oacc[nb][j] = 0.f;

    const int ld_row = tid >> 5;          // 0..7
    const int ld_c4  = (tid & 31) << 2;   // 0..124

    // Prologue: async-load tile 0 into buffer 0.
    {
        #pragma unroll
        for (int p = 0; p < 8; p++) {
            int kr = ld_row + p * 8;
            cp_async16(&sK0[kr * LDQ + ld_c4], &g_k[(size_t)kr * D_HEAD + ld_c4]);
            cp_async16(&sV0[kr * LDQ + ld_c4], &g_v[(size_t)kr * D_HEAD + ld_c4]);
        }
        CP_COMMIT();
    }

    const int NT = N_TOK / BN;            // 128 tiles
    const int row = tid >> 2;             // softmax row
    const int qq  = tid & 3;              // 16-col quarter

    for (int t = 0; t < NT; t++) {
        float* sK = sK0 + (t & 1) * SMEM_KV;
        float* sV = sV0 + (t & 1) * SMEM_KV;

        // Issue async load of tile t+1 into the other buffer.
        if (t + 1 < NT) {
            float* nK = sK0 + ((t + 1) & 1) * SMEM_KV;
            float* nV = sV0 + ((t + 1) & 1) * SMEM_KV;
            size_t gbase = (size_t)(t + 1) * BN * D_HEAD;
            #pragma unroll
            for (int p = 0; p < 8; p++) {
                int kr = ld_row + p * 8;
                cp_async16(&nK[kr * LDQ + ld_c4], &g_k[gbase + (size_t)kr * D_HEAD + ld_c4]);
                cp_async16(&nV[kr * LDQ + ld_c4], &g_v[gbase + (size_t)kr * D_HEAD + ld_c4]);
            }
            CP_COMMIT();
            CP_WAIT(1);
        } else {
            CP_WAIT(0);
        }
        __syncthreads();

        // ---- S = Qs @ K^T via tf32 mma: warp covers 16 rows x 32 cols ----
        float sacc[4][4];
        #pragma unroll
        for (int nb = 0; nb < 4; nb++)
            #pragma unroll
            for (int j = 0; j < 4; j++) sacc[nb][j] = 0.f;

        #pragma unroll
        for (int ks = 0; ks < 16; ks++) {
            int d0 = ks * 8;
            int arow = rg + lq;
            uint32_t a0 = fu(sQ[arow * LDQ + d0 + lr]);
            uint32_t a1 = fu(sQ[(arow + 8) * LDQ + d0 + lr]);
            uint32_t a2 = fu(sQ[arow * LDQ + d0 + lr + 4]);
            uint32_t a3 = fu(sQ[(arow + 8) * LDQ + d0 + lr + 4]);
            #pragma unroll
            for (int nb = 0; nb < 4; nb++) {
                int brow = wc * 32 + nb * 8 + lq;
                uint32_t b0 = fu(sK[brow * LDQ + d0 + lr]);
                uint32_t b1 = fu(sK[brow * LDQ + d0 + lr + 4]);
                mma_tf32(sacc[nb], a0, a1, a2, a3, b0, b1);
            }
        }
        // Store S fragments to smem (float2).
        {
            int r0 = rg + lq;
            #pragma unroll
            for (int nb = 0; nb < 4; nb++) {
                int c = wc * 32 + nb * 8 + 2 * lr;
                *(float2*)&sS[r0 * LDS_S + c]       = make_float2(sacc[nb][0], sacc[nb][1]);
                *(float2*)&sS[(r0 + 8) * LDS_S + c] = make_float2(sacc[nb][2], sacc[nb][3]);
            }
        }
        __syncthreads();

        // ---- Online softmax (thread-per-row, 4 quarters) ----
        const int base = row * LDS_S + qq * 16;
        float pm = -INFINITY;
        #pragma unroll
        for (int cc = 0; cc < 16; cc++) pm = fmaxf(pm, sS[base + cc]);
        sRed[qq * 64 + row] = pm;
        __syncthreads();

        if (tid < BM) {
            float mt = fmaxf(fmaxf(sRed[tid], sRed[64 + tid]),
                             fmaxf(sRed[128 + tid], sRed[192 + tid]));
            float mold = sM[tid];
            float mnew = fmaxf(mold, mt);
            sM[tid]     = mnew;
            sAlpha[tid] = __expf(mold - mnew);
        }
        __syncthreads();

        float mnew = sM[row];
        float psum = 0.f;
        #pragma unroll
        for (int cc = 0; cc < 16; cc++) {
            float p = tf32_rna(__expf(sS[base + cc] - mnew));
            sS[base + cc] = p;
            psum += p;
        }
        sRed[qq * 64 + row] = psum;
        __syncthreads();

        if (tid < BM) {
            sL[tid] = sL[tid] * sAlpha[tid] +
                      (sRed[tid] + sRed[64 + tid] + sRed[128 + tid] + sRed[192 + tid]);
        }

        // Rescale running O by alpha.
        {
            float a_lo = sAlpha[rg + lq];
            float a_hi = sAlpha[rg + lq + 8];
            #pragma unroll
            for (int nb = 0; nb < 8; nb++) {
                oacc[nb][0] *= a_lo; oacc[nb][1] *= a_lo;
                oacc[nb][2] *= a_hi; oacc[nb][3] *= a_hi;
            }
        }

        // ---- O += P @ V via tf32 mma: warp covers 16 rows x 64 cols ----
        #pragma unroll
        for (int ks = 0; ks < 8; ks++) {
            int kk0 = ks * 8;
            int arow = rg + lq;
            uint32_t a0 = fu(sS[arow * LDS_S + kk0 + lr]);
            uint32_t a1 = fu(sS[(arow + 8) * LDS_S + kk0 + lr]);
            uint32_t a2 = fu(sS[arow * LDS_S + kk0 + lr + 4]);
            uint32_t a3 = fu(sS[(arow + 8) * LDS_S + kk0 + lr + 4]);
            #pragma unroll
            for (int nb = 0; nb < 8; nb++) {
                int vcol = wc * 64 + nb * 8 + lq;
                uint32_t b0 = fu(sV[(kk0 + lr) * LDQ + vcol]);
                uint32_t b1 = fu(sV[(kk0 + lr + 4) * LDQ + vcol]);
                mma_tf32(oacc[nb], a0, a1, a2, a3, b0, b1);
            }
        }
        __syncthreads();
    }

    // Epilogue: divide by l, store O fragments.
    {
        int r0 = rg + lq;
        float linv_lo = 1.f / sL[r0];
        float linv_hi = 1.f / sL[r0 + 8];
        #pragma unroll
        for (int nb = 0; nb < 8; nb++) {
            int c = wc * 64 + nb * 8 + 2 * lr;
            *(float2*)&out[(size_t)(q0 + r0) * D_HEAD + c] =
                make_float2(oacc[nb][0] * linv_lo, oacc[nb][1] * linv_lo);
            *(float2*)&out[(size_t)(q0 + r0 + 8) * D_HEAD + c] =
                make_float2(oacc[nb][2] * linv_hi, oacc[nb][3] * linv_hi);
        }
    }
}

// ---------------------------------------------------------------------------
extern "C" void kernel_launch(void* const* d_in, const int* in_sizes, int n_in,
                              void* d_out, int out_size)
{
    const float* z  = (const float*)d_in[0];
    const float* Wq = (const float*)d_in[1];
    const float* bq = (const float*)d_in[2];
    const float* Wk = (const float*)d_in[3];
    const float* bk = (const float*)d_in[4];
    const float* Wv = (const float*)d_in[5];
    const float* bv = (const float*)d_in[6];
    float* out = (float*)d_out;

    cudaFuncSetAttribute(attn_kernel, cudaFuncAttributeMaxDynamicSharedMemorySize,
                         ATTN_SMEM_BYTES);

    dim3 gqkv(N_TOK / 128, 3);
    qkv_kernel<<<gqkv, 256>>>(z, Wq, bq, Wk, bk, Wv, bv);

    attn_kernel<<<N_TOK / BM, 256, ATTN_SMEM_BYTES>>>(out);
}

// round 3
// speedup vs baseline: 3.3290x; 1.7024x over previous
#include <cuda_runtime.h>
#include <math.h>
#include <stdint.h>

#define N_TOK  8192
#define IN_DIM 1024
#define D_HEAD 128
#define BM 64
#define BN 64

// Scratch (allocation-free rule).
__device__ float g_q[N_TOK * D_HEAD];    // [n][d_perm], pre-scaled by 1/sqrt(d), tf32
__device__ float g_k[N_TOK * D_HEAD];    // [n][d_perm], tf32
__device__ float g_vt[D_HEAD * N_TOK];   // [d][key_perm], tf32
__device__ float g_zr[N_TOK * IN_DIM];   // z rounded to tf32 (RNA)
__device__ float g_wr[3 * IN_DIM * D_HEAD]; // Wq/Wk/Wv rounded to tf32

__device__ __forceinline__ float tf32_rna(float x) {
    uint32_t u;
    asm("cvt.rna.tf32.f32 %0, %1;" : "=r"(u) : "f"(x));
    return __uint_as_float(u);
}
__device__ __forceinline__ uint32_t fu(float x) { return __float_as_uint(x); }

__device__ __forceinline__ void mma_tf32(float (&d)[4],
    uint32_t a0, uint32_t a1, uint32_t a2, uint32_t a3,
    uint32_t b0, uint32_t b1)
{
    asm volatile(
        "mma.sync.aligned.m16n8k8.row.col.f32.tf32.tf32.f32 "
        "{%0,%1,%2,%3}, {%4,%5,%6,%7}, {%8,%9}, {%0,%1,%2,%3};\n"
        : "+f"(d[0]), "+f"(d[1]), "+f"(d[2]), "+f"(d[3])
        : "r"(a0), "r"(a1), "r"(a2), "r"(a3), "r"(b0), "r"(b1));
}

__device__ __forceinline__ void cp_async16(void* sdst, const void* gsrc) {
    uint32_t s = (uint32_t)__cvta_generic_to_shared(sdst);
    asm volatile("cp.async.cg.shared.global [%0], [%1], 16;\n" :: "r"(s), "l"(gsrc));
}
#define CP_COMMIT() asm volatile("cp.async.commit_group;\n" ::: "memory")
#define CP_WAIT(n)  asm volatile("cp.async.wait_group %0;\n" :: "n"(n) : "memory")

// ---------------------------------------------------------------------------
// Kernel 0: RNA-round z and W to tf32 (unbiased; raw fp32 into mma truncates).
// ---------------------------------------------------------------------------
__global__ __launch_bounds__(256) void prep_kernel(
    const float* __restrict__ z,
    const float* __restrict__ Wq, const float* __restrict__ Wk,
    const float* __restrict__ Wv)
{
    const int NZ4 = (N_TOK * IN_DIM) / 4;
    const int NW4 = (IN_DIM * D_HEAD) / 4;
    int stride = gridDim.x * blockDim.x;
    for (int i = blockIdx.x * blockDim.x + threadIdx.x; i < NZ4; i += stride) {
        float4 v = ((const float4*)z)[i];
        v.x = tf32_rna(v.x); v.y = tf32_rna(v.y);
        v.z = tf32_rna(v.z); v.w = tf32_rna(v.w);
        ((float4*)g_zr)[i] = v;
    }
    for (int i = blockIdx.x * blockDim.x + threadIdx.x; i < NW4; i += stride) {
        float4 a = ((const float4*)Wq)[i], b = ((const float4*)Wk)[i],
               c = ((const float4*)Wv)[i];
        a.x = tf32_rna(a.x); a.y = tf32_rna(a.y); a.z = tf32_rna(a.z); a.w = tf32_rna(a.w);
        b.x = tf32_rna(b.x); b.y = tf32_rna(b.y); b.z = tf32_rna(b.z); b.w = tf32_rna(b.w);
        c.x = tf32_rna(c.x); c.y = tf32_rna(c.y); c.z = tf32_rna(c.z); c.w = tf32_rna(c.w);
        ((float4*)g_wr)[i] = a;
        ((float4*)(g_wr + IN_DIM * D_HEAD))[i] = b;
        ((float4*)(g_wr + 2 * IN_DIM * D_HEAD))[i] = c;
    }
}

// ---------------------------------------------------------------------------
// Kernel 1: QKV projection on tf32 tensor cores. CTA: 128 rows x 128 cols.
// Q/K written with d-permuted cols; V written transposed [d][key_perm].
// ---------------------------------------------------------------------------
#define QK_KS 32
#define ZP 36
#define WP 136
#define TP 129
#define QKV_SMEM_FLOATS (2 * 128 * ZP + 2 * 32 * WP)   // 17920 (> 128*129 alias)
#define QKV_SMEM_BYTES  (QKV_SMEM_FLOATS * 4)

__global__ __launch_bounds__(256) void qkv_kernel(
    const float* __restrict__ bq, const float* __restrict__ bk,
    const float* __restrict__ bv)
{
    extern __shared__ float sm[];
    float* sZ = sm;                   // [2][128][36]
    float* sW = sm + 2 * 128 * ZP;    // [2][32][136]

    const int mat = blockIdx.y;
    const float* W = g_wr + (size_t)mat * IN_DIM * D_HEAD;
    const float* b = (mat == 0) ? bq : (mat == 1) ? bk : bv;

    const int tid = threadIdx.x, lane = tid & 31, wid = tid >> 5;
    const int rg = (wid & 3) * 32, wc = wid >> 2;
    const int lq = lane >> 2, lr = lane & 3;
    const int row0 = blockIdx.x * 128;

    float acc[2][8][4] = {};

    auto load_tiles = [&](int kt, int buf) {
        float* dZ = sZ + buf * 128 * ZP;
        float* dW = sW + buf * 32 * WP;
        #pragma unroll
        for (int i = 0; i < 4; i++) {
            int c = tid + 256 * i;
            int r = c >> 3, c4 = (c & 7) * 4;
            cp_async16(&dZ[r * ZP + c4],
                       &g_zr[(size_t)(row0 + r) * IN_DIM + kt * QK_KS + c4]);
        }
        #pragma unroll
        for (int i = 0; i < 4; i++) {
            int c = tid + 256 * i;
            int r = c >> 5, c4 = (c & 31) * 4;
            cp_async16(&dW[r * WP + c4], &W[(size_t)(kt * QK_KS + r) * D_HEAD + c4]);
        }
        CP_COMMIT();
    };

    load_tiles(0, 0);
    const int NKT = IN_DIM / QK_KS;
    for (int kt = 0; kt < NKT; kt++) {
        if (kt + 1 < NKT) { load_tiles(kt + 1, (kt + 1) & 1); CP_WAIT(1); }
        else CP_WAIT(0);
        __syncthreads();
        float* cZ = sZ + (kt & 1) * 128 * ZP;
        float* cW = sW + (kt & 1) * 32 * WP;
        #pragma unroll
        for (int ks = 0; ks < 4; ks++) {
            int d0 = ks * 8;
            uint32_t A[2][4];
            #pragma unroll
            for (int mt = 0; mt < 2; mt++) {
                int r = rg + mt * 16 + lq;
                A[mt][0] = fu(cZ[r * ZP + d0 + lr]);
                A[mt][1] = fu(cZ[(r + 8) * ZP + d0 + lr]);
                A[mt][2] = fu(cZ[r * ZP + d0 + lr + 4]);
                A[mt][3] = fu(cZ[(r + 8) * ZP + d0 + lr + 4]);
            }
            #pragma unroll
            for (int nb = 0; nb < 8; nb++) {
                int ncol = wc * 64 + nb * 8 + lq;
                uint32_t b0 = fu(cW[(d0 + lr) * WP + ncol]);
                uint32_t b1 = fu(cW[(d0 + lr + 4) * WP + ncol]);
                mma_tf32(acc[0][nb], A[0][0], A[0][1], A[0][2], A[0][3], b0, b1);
                mma_tf32(acc[1][nb], A[1][0], A[1][1], A[1][2], A[1][3], b0, b1);
            }
        }
        __syncthreads();
    }

    // Epilogue
    const int s_off = (lr < 2) ? 4 * lr : 4 * lr - 7;   // perm slot of col 2lr
    if (mat < 2) {
        float* g = (mat == 0) ? g_q : g_k;
        const float scl = (mat == 0) ? 0.08838834764831845f : 1.0f;
        #pragma unroll
        for (int mt = 0; mt < 2; mt++)
            #pragma unroll
            for (int nb = 0; nb < 8; nb++) {
                int cbase = wc * 64 + nb * 8;
                int c0 = cbase + 2 * lr;
                float b0v = b[c0], b1v = b[c0 + 1];
                int s0 = cbase + s_off;
                size_t r = row0 + rg + mt * 16 + lq;
                g[r * D_HEAD + s0]           = tf32_rna((acc[mt][nb][0] + b0v) * scl);
                g[r * D_HEAD + s0 + 2]       = tf32_rna((acc[mt][nb][1] + b1v) * scl);
                g[(r + 8) * D_HEAD + s0]     = tf32_rna((acc[mt][nb][2] + b0v) * scl);
                g[(r + 8) * D_HEAD + s0 + 2] = tf32_rna((acc[mt][nb][3] + b1v) * scl);
            }
    } else {
        float* sT = sm;   // [128][129] alias (loop buffers dead after last sync)
        #pragma unroll
        for (int mt = 0; mt < 2; mt++)
            #pragma unroll
            for (int nb = 0; nb < 8; nb++) {
                int c0 = wc * 64 + nb * 8 + 2 * lr;
                float b0v = b[c0], b1v = b[c0 + 1];
                int r = rg + mt * 16 + lq;
                sT[r * TP + c0]           = tf32_rna(acc[mt][nb][0] + b0v);
                sT[r * TP + c0 + 1]       = tf32_rna(acc[mt][nb][1] + b1v);
                sT[(r + 8) * TP + c0]     = tf32_rna(acc[mt][nb][2] + b0v);
                sT[(r + 8) * TP + c0 + 1] = tf32_rna(acc[mt][nb][3] + b1v);
            }
        __syncthreads();
        #pragma unroll
        for (int i = 0; i < 64; i++) {
            int idx = tid + 256 * i;
            int d = idx >> 7;
            int key = idx & 127;
            int kp = (key & ~7) + 2 * (key & 3) + ((key & 7) >> 2);
            g_vt[(size_t)d * N_TOK + row0 + kp] = sT[key * TP + d];
        }
    }
}

// ---------------------------------------------------------------------------
// Kernel 2: flash attention, tf32 mma, 64-bit fragment loads via k-perm,
// register softmax (shfl). 8 warps = 4 row-groups x 2 halves.
// ---------------------------------------------------------------------------
#define PQ 136          // sQ/sK pitch (floats)
#define PV 72           // sVt pitch
#define PS 72           // sS (P) pitch
#define SM_Q   (BM * PQ)                 // 8704
#define SM_K   (BN * PQ)                 // 8704 per buf
#define SM_VT  (D_HEAD * PV)             // 9216 per buf
#define SM_S   (BM * PS)                 // 4608
#define ATTN_SMEM_FLOATS (SM_Q + 2 * SM_K + 2 * SM_VT + SM_S + 3 * BM + 4 * BM)
#define ATTN_SMEM_BYTES  (ATTN_SMEM_FLOATS * 4)

__global__ __launch_bounds__(256) void attn_kernel(float* __restrict__ out)
{
    extern __shared__ float smem[];
    float* sQ   = smem;
    float* sK0  = sQ + SM_Q;
    float* sVt0 = sK0 + 2 * SM_K;
    float* sS   = sVt0 + 2 * SM_VT;
    float* sM     = sS + SM_S;
    float* sL     = sM + BM;
    float* sAlpha = sL + BM;
    float* sRedM  = sAlpha + BM;     // [2][64]
    float* sRedS  = sRedM + 2 * BM;  // [2][64]

    const int tid = threadIdx.x, lane = tid & 31, wid = tid >> 5;
    const int rg = (wid & 3) * 16, wc = wid >> 2;
    const int lq = lane >> 2, lr = lane & 3;
    const int q0 = blockIdx.x * BM;
    const int s_off = (lr < 2) ? 4 * lr : 4 * lr - 7;

    if (tid < BM) { sM[tid] = -INFINITY; sL[tid] = 0.f; }

    // Prologue: Q tile + KV tile 0.
    #pragma unroll
    for (int i = 0; i < 8; i++) {
        int c = tid + 256 * i;
        int r = c >> 5, c4 = (c & 31) * 4;
        cp_async16(&sQ[r * PQ + c4], &g_q[(size_t)(q0 + r) * D_HEAD + c4]);
    }
    #pragma unroll
    for (int i = 0; i < 8; i++) {
        int c = tid + 256 * i;
        int r = c >> 5, c4 = (c & 31) * 4;
        cp_async16(&sK0[r * PQ + c4], &g_k[(size_t)r * D_HEAD + c4]);
    }
    #pragma unroll
    for (int i = 0; i < 8; i++) {
        int c = tid + 256 * i;
        int d = c >> 4, c4 = (c & 15) * 4;
        cp_async16(&sVt0[d * PV + c4], &g_vt[(size_t)d * N_TOK + c4]);
    }
    CP_COMMIT();

    float oacc[8][4] = {};
    const int NT = N_TOK / BN;

    for (int t = 0; t < NT; t++) {
        float* sK  = sK0  + (t & 1) * SM_K;
        float* sVt = sVt0 + (t & 1) * SM_VT;

        if (t + 1 < NT) {
            float* nK  = sK0  + ((t + 1) & 1) * SM_K;
            float* nVt = sVt0 + ((t + 1) & 1) * SM_VT;
            size_t kg = (size_t)(t + 1) * BN;
            #pragma unroll
            for (int i = 0; i < 8; i++) {
                int c = tid + 256 * i;
                int r = c >> 5, c4 = (c & 31) * 4;
                cp_async16(&nK[r * PQ + c4], &g_k[(kg + r) * D_HEAD + c4]);
            }
            #pragma unroll
            for (int i = 0; i < 8; i++) {
                int c = tid + 256 * i;
                int d = c >> 4, c4 = (c & 15) * 4;
                cp_async16(&nVt[d * PV + c4], &g_vt[(size_t)d * N_TOK + kg + c4]);
            }
            CP_COMMIT();
            CP_WAIT(1);
        } else {
            CP_WAIT(0);
        }
        __syncthreads();                                      // (A)

        // ---- S = Qs @ K^T ----
        float sacc[4][4] = {};
        #pragma unroll
        for (int ks = 0; ks < 16; ks++) {
            int d0 = ks * 8;
            float2 fa0 = *(const float2*)&sQ[(rg + lq) * PQ + d0 + 2 * lr];
            float2 fa1 = *(const float2*)&sQ[(rg + lq + 8) * PQ + d0 + 2 * lr];
            uint32_t a0 = fu(fa0.x), a2 = fu(fa0.y);
            uint32_t a1 = fu(fa1.x), a3 = fu(fa1.y);
            #pragma unroll
            for (int nb = 0; nb < 4; nb++) {
                float2 fb = *(const float2*)&sK[(wc * 32 + nb * 8 + lq) * PQ + d0 + 2 * lr];
                mma_tf32(sacc[nb], a0, a1, a2, a3, fu(fb.x), fu(fb.y));
            }
        }

        // ---- register softmax: row max over this half ----
        float m_lo = -INFINITY, m_hi = -INFINITY;
        #pragma unroll
        for (int nb = 0; nb < 4; nb++) {
            m_lo = fmaxf(m_lo, fmaxf(sacc[nb][0], sacc[nb][1]));
            m_hi = fmaxf(m_hi, fmaxf(sacc[nb][2], sacc[nb][3]));
        }
        m_lo = fmaxf(m_lo, __shfl_xor_sync(0xffffffffu, m_lo, 1));
        m_lo = fmaxf(m_lo, __shfl_xor_sync(0xffffffffu, m_lo, 2));
        m_hi = fmaxf(m_hi, __shfl_xor_sync(0xffffffffu, m_hi, 1));
        m_hi = fmaxf(m_hi, __shfl_xor_sync(0xffffffffu, m_hi, 2));
        if (lr == 0) {
            sRedM[wc * 64 + rg + lq]     = m_lo;
            sRedM[wc * 64 + rg + lq + 8] = m_hi;
        }
        __syncthreads();                                      // (B1)

        if (tid < BM) {
            float mt = fmaxf(sRedM[tid], sRedM[64 + tid]);
            float mold = sM[tid];
            float mnew = fmaxf(mold, mt);
            sM[tid] = mnew;
            sAlpha[tid] = __expf(mold - mnew);
        }
        __syncthreads();                                      // (B2)

        // ---- exp + P store (key-permuted) + partial sums ----
        float mn_lo = sM[rg + lq],     mn_hi = sM[rg + lq + 8];
        float al_lo = sAlpha[rg + lq], al_hi = sAlpha[rg + lq + 8];
        float sum_lo = 0.f, sum_hi = 0.f;
        #pragma unroll
        for (int nb = 0; nb < 4; nb++) {
            int cb = wc * 32 + nb * 8;
            float p0 = tf32_rna(__expf(sacc[nb][0] - mn_lo));
            float p1 = tf32_rna(__expf(sacc[nb][1] - mn_lo));
            float p2 = tf32_rna(__expf(sacc[nb][2] - mn_hi));
            float p3 = tf32_rna(__expf(sacc[nb][3] - mn_hi));
            sum_lo += p0 + p1; sum_hi += p2 + p3;
            sS[(rg + lq) * PS + cb + s_off]         = p0;
            sS[(rg + lq) * PS + cb + s_off + 2]     = p1;
            sS[(rg + lq + 8) * PS + cb + s_off]     = p2;
            sS[(rg + lq + 8) * PS + cb + s_off + 2] = p3;
        }
        sum_lo += __shfl_xor_sync(0xffffffffu, sum_lo, 1);
        sum_lo += __shfl_xor_sync(0xffffffffu, sum_lo, 2);
        sum_hi += __shfl_xor_sync(0xffffffffu, sum_hi, 1);
        sum_hi += __shfl_xor_sync(0xffffffffu, sum_hi, 2);
        if (lr == 0) {
            sRedS[wc * 64 + rg + lq]     = sum_lo;
            sRedS[wc * 64 + rg + lq + 8] = sum_hi;
        }
        // rescale running O by alpha
        #pragma unroll
        for (int nb = 0; nb < 8; nb++) {
            oacc[nb][0] *= al_lo; oacc[nb][1] *= al_lo;
            oacc[nb][2] *= al_hi; oacc[nb][3] *= al_hi;
        }
        __syncthreads();                                      // (C)

        if (tid < BM)
            sL[tid] = sL[tid] * sAlpha[tid] + sRedS[tid] + sRedS[64 + tid];

        // ---- O += P @ V (V^T layout, both sides key-permuted) ----
        #pragma unroll
        for (int k2 = 0; k2 < 8; k2++) {
            int kk0 = k2 * 8;
            float2 fa0 = *(const float2*)&sS[(rg + lq) * PS + kk0 + 2 * lr];
            float2 fa1 = *(const float2*)&sS[(rg + lq + 8) * PS + kk0 + 2 * lr];
            uint32_t a0 = fu(fa0.x), a2 = fu(fa0.y);
            uint32_t a1 = fu(fa1.x), a3 = fu(fa1.y);
            #pragma unroll
            for (int nb = 0; nb < 8; nb++) {
                int vcol = wc * 64 + nb * 8 + lq;
                float2 fb = *(const float2*)&sVt[vcol * PV + kk0 + 2 * lr];
                mma_tf32(oacc[nb], a0, a1, a2, a3, fu(fb.x), fu(fb.y));
            }
        }
        __syncthreads();                                      // (D)
    }

    // Epilogue
    float linv_lo = 1.f / sL[rg + lq];
    float linv_hi = 1.f / sL[rg + lq + 8];
    #pragma unroll
    for (int nb = 0; nb < 8; nb++) {
        int c = wc * 64 + nb * 8 + 2 * lr;
        *(float2*)&out[(size_t)(q0 + rg + lq) * D_HEAD + c] =
            make_float2(oacc[nb][0] * linv_lo, oacc[nb][1] * linv_lo);
        *(float2*)&out[(size_t)(q0 + rg + lq + 8) * D_HEAD + c] =
            make_float2(oacc[nb][2] * linv_hi, oacc[nb][3] * linv_hi);
    }
}

// ---------------------------------------------------------------------------
extern "C" void kernel_launch(void* const* d_in, const int* in_sizes, int n_in,
                              void* d_out, int out_size)
{
    const float* z  = (const float*)d_in[0];
    const float* Wq = (const float*)d_in[1];
    const float* bq = (const float*)d_in[2];
    const float* Wk = (const float*)d_in[3];
    const float* bk = (const float*)d_in[4];
    const float* Wv = (const float*)d_in[5];
    const float* bv = (const float*)d_in[6];
    float* out = (float*)d_out;

    cudaFuncSetAttribute(qkv_kernel, cudaFuncAttributeMaxDynamicSharedMemorySize,
                         QKV_SMEM_BYTES);
    cudaFuncSetAttribute(attn_kernel, cudaFuncAttributeMaxDynamicSharedMemorySize,
                         ATTN_SMEM_BYTES);

    prep_kernel<<<1024, 256>>>(z, Wq, Wk, Wv);

    dim3 gqkv(N_TOK / 128, 3);
    qkv_kernel<<<gqkv, 256, QKV_SMEM_BYTES>>>(bq, bk, bv);

    attn_kernel<<<N_TOK / BM, 256, ATTN_SMEM_BYTES>>>(out);
}

// round 4
// speedup vs baseline: 4.2586x; 1.2792x over previous
#include <cuda_runtime.h>
#include <math.h>
#include <stdint.h>

#define N_TOK  8192
#define IN_DIM 1024
#define D_HEAD 128
#define BM 64
#define BN 64

// Scratch (allocation-free rule).
__device__ float g_q[N_TOK * D_HEAD];    // [n][d_perm], scaled by log2e/sqrt(d), tf32
__device__ float g_k[N_TOK * D_HEAD];    // [n][d_perm], tf32
__device__ float g_vt[D_HEAD * N_TOK];   // [d][key] natural order, tf32
__device__ float g_zr[N_TOK * IN_DIM];   // z rounded to tf32 (RNA)
__device__ float g_wr[3 * IN_DIM * D_HEAD]; // Wq/Wk/Wv rounded to tf32

__device__ __forceinline__ float tf32_rna(float x) {
    uint32_t u;
    asm("cvt.rna.tf32.f32 %0, %1;" : "=r"(u) : "f"(x));
    return __uint_as_float(u);
}
__device__ __forceinline__ uint32_t fu(float x) { return __float_as_uint(x); }
__device__ __forceinline__ float ex2(float x) {
    float y;
    asm("ex2.approx.ftz.f32 %0, %1;" : "=f"(y) : "f"(x));
    return y;
}

__device__ __forceinline__ void mma_tf32(float (&d)[4],
    uint32_t a0, uint32_t a1, uint32_t a2, uint32_t a3,
    uint32_t b0, uint32_t b1)
{
    asm volatile(
        "mma.sync.aligned.m16n8k8.row.col.f32.tf32.tf32.f32 "
        "{%0,%1,%2,%3}, {%4,%5,%6,%7}, {%8,%9}, {%0,%1,%2,%3};\n"
        : "+f"(d[0]), "+f"(d[1]), "+f"(d[2]), "+f"(d[3])
        : "r"(a0), "r"(a1), "r"(a2), "r"(a3), "r"(b0), "r"(b1));
}

__device__ __forceinline__ void cp_async16(void* sdst, const void* gsrc) {
    uint32_t s = (uint32_t)__cvta_generic_to_shared(sdst);
    asm volatile("cp.async.cg.shared.global [%0], [%1], 16;\n" :: "r"(s), "l"(gsrc));
}
#define CP_COMMIT() asm volatile("cp.async.commit_group;\n" ::: "memory")
#define CP_WAIT(n)  asm volatile("cp.async.wait_group %0;\n" :: "n"(n) : "memory")

// ---------------------------------------------------------------------------
// Kernel 0: RNA-round z and W to tf32.
// ---------------------------------------------------------------------------
__global__ __launch_bounds__(256) void prep_kernel(
    const float* __restrict__ z,
    const float* __restrict__ Wq, const float* __restrict__ Wk,
    const float* __restrict__ Wv)
{
    const int NZ4 = (N_TOK * IN_DIM) / 4;
    const int NW4 = (IN_DIM * D_HEAD) / 4;
    int stride = gridDim.x * blockDim.x;
    for (int i = blockIdx.x * blockDim.x + threadIdx.x; i < NZ4; i += stride) {
        float4 v = ((const float4*)z)[i];
        v.x = tf32_rna(v.x); v.y = tf32_rna(v.y);
        v.z = tf32_rna(v.z); v.w = tf32_rna(v.w);
        ((float4*)g_zr)[i] = v;
    }
    for (int i = blockIdx.x * blockDim.x + threadIdx.x; i < NW4; i += stride) {
        float4 a = ((const float4*)Wq)[i], b = ((const float4*)Wk)[i],
               c = ((const float4*)Wv)[i];
        a.x = tf32_rna(a.x); a.y = tf32_rna(a.y); a.z = tf32_rna(a.z); a.w = tf32_rna(a.w);
        b.x = tf32_rna(b.x); b.y = tf32_rna(b.y); b.z = tf32_rna(b.z); b.w = tf32_rna(b.w);
        c.x = tf32_rna(c.x); c.y = tf32_rna(c.y); c.z = tf32_rna(c.z); c.w = tf32_rna(c.w);
        ((float4*)g_wr)[i] = a;
        ((float4*)(g_wr + IN_DIM * D_HEAD))[i] = b;
        ((float4*)(g_wr + 2 * IN_DIM * D_HEAD))[i] = c;
    }
}

// ---------------------------------------------------------------------------
// Kernel 1: QKV projection, tf32 mma. Q/K written d-permuted; V transposed.
// ---------------------------------------------------------------------------
#define QK_KS 32
#define ZP 36
#define WP 136
#define TP 129
#define QKV_SMEM_FLOATS (2 * 128 * ZP + 2 * 32 * WP)
#define QKV_SMEM_BYTES  (QKV_SMEM_FLOATS * 4)

__global__ __launch_bounds__(256) void qkv_kernel(
    const float* __restrict__ bq, const float* __restrict__ bk,
    const float* __restrict__ bv)
{
    extern __shared__ float sm[];
    float* sZ = sm;                   // [2][128][36]
    float* sW = sm + 2 * 128 * ZP;    // [2][32][136]

    const int mat = blockIdx.y;
    const float* W = g_wr + (size_t)mat * IN_DIM * D_HEAD;
    const float* b = (mat == 0) ? bq : (mat == 1) ? bk : bv;

    const int tid = threadIdx.x, lane = tid & 31, wid = tid >> 5;
    const int rg = (wid & 3) * 32, wc = wid >> 2;
    const int lq = lane >> 2, lr = lane & 3;
    const int row0 = blockIdx.x * 128;

    float acc[2][8][4] = {};

    auto load_tiles = [&](int kt, int buf) {
        float* dZ = sZ + buf * 128 * ZP;
        float* dW = sW + buf * 32 * WP;
        #pragma unroll
        for (int i = 0; i < 4; i++) {
            int c = tid + 256 * i;
            int r = c >> 3, c4 = (c & 7) * 4;
            cp_async16(&dZ[r * ZP + c4],
                       &g_zr[(size_t)(row0 + r) * IN_DIM + kt * QK_KS + c4]);
        }
        #pragma unroll
        for (int i = 0; i < 4; i++) {
            int c = tid + 256 * i;
            int r = c >> 5, c4 = (c & 31) * 4;
            cp_async16(&dW[r * WP + c4], &W[(size_t)(kt * QK_KS + r) * D_HEAD + c4]);
        }
        CP_COMMIT();
    };

    load_tiles(0, 0);
    const int NKT = IN_DIM / QK_KS;
    for (int kt = 0; kt < NKT; kt++) {
        if (kt + 1 < NKT) { load_tiles(kt + 1, (kt + 1) & 1); CP_WAIT(1); }
        else CP_WAIT(0);
        __syncthreads();
        float* cZ = sZ + (kt & 1) * 128 * ZP;
        float* cW = sW + (kt & 1) * 32 * WP;
        #pragma unroll
        for (int ks = 0; ks < 4; ks++) {
            int d0 = ks * 8;
            uint32_t A[2][4];
            #pragma unroll
            for (int mt = 0; mt < 2; mt++) {
                int r = rg + mt * 16 + lq;
                A[mt][0] = fu(cZ[r * ZP + d0 + lr]);
                A[mt][1] = fu(cZ[(r + 8) * ZP + d0 + lr]);
                A[mt][2] = fu(cZ[r * ZP + d0 + lr + 4]);
                A[mt][3] = fu(cZ[(r + 8) * ZP + d0 + lr + 4]);
            }
            #pragma unroll
            for (int nb = 0; nb < 8; nb++) {
                int ncol = wc * 64 + nb * 8 + lq;
                uint32_t b0 = fu(cW[(d0 + lr) * WP + ncol]);
                uint32_t b1 = fu(cW[(d0 + lr + 4) * WP + ncol]);
                mma_tf32(acc[0][nb], A[0][0], A[0][1], A[0][2], A[0][3], b0, b1);
                mma_tf32(acc[1][nb], A[1][0], A[1][1], A[1][2], A[1][3], b0, b1);
            }
        }
        __syncthreads();
    }

    // Epilogue
    const int s_off = (lr < 2) ? 4 * lr : 4 * lr - 7;   // perm slot of col 2lr
    if (mat < 2) {
        float* g = (mat == 0) ? g_q : g_k;
        // log2e / sqrt(128) folded into Q so softmax runs in exp2 domain.
        const float scl = (mat == 0) ? 0.12753785626672556f : 1.0f;
        #pragma unroll
        for (int mt = 0; mt < 2; mt++)
            #pragma unroll
            for (int nb = 0; nb < 8; nb++) {
                int cbase = wc * 64 + nb * 8;
                int c0 = cbase + 2 * lr;
                float b0v = b[c0], b1v = b[c0 + 1];
                int s0 = cbase + s_off;
                size_t r = row0 + rg + mt * 16 + lq;
                g[r * D_HEAD + s0]           = tf32_rna((acc[mt][nb][0] + b0v) * scl);
                g[r * D_HEAD + s0 + 2]       = tf32_rna((acc[mt][nb][1] + b1v) * scl);
                g[(r + 8) * D_HEAD + s0]     = tf32_rna((acc[mt][nb][2] + b0v) * scl);
                g[(r + 8) * D_HEAD + s0 + 2] = tf32_rna((acc[mt][nb][3] + b1v) * scl);
            }
    } else {
        float* sT = sm;   // [128][129] alias
        #pragma unroll
        for (int mt = 0; mt < 2; mt++)
            #pragma unroll
            for (int nb = 0; nb < 8; nb++) {
                int c0 = wc * 64 + nb * 8 + 2 * lr;
                float b0v = b[c0], b1v = b[c0 + 1];
                int r = rg + mt * 16 + lq;
                sT[r * TP + c0]           = tf32_rna(acc[mt][nb][0] + b0v);
                sT[r * TP + c0 + 1]       = tf32_rna(acc[mt][nb][1] + b1v);
                sT[(r + 8) * TP + c0]     = tf32_rna(acc[mt][nb][2] + b0v);
                sT[(r + 8) * TP + c0 + 1] = tf32_rna(acc[mt][nb][3] + b1v);
            }
        __syncthreads();
        // V transposed, natural key order (identity perm cancels frag layouts).
        #pragma unroll
        for (int i = 0; i < 64; i++) {
            int idx = tid + 256 * i;
            int d = idx >> 7;
            int key = idx & 127;
            g_vt[(size_t)d * N_TOK + row0 + key] = sT[key * TP + d];
        }
    }
}

// ---------------------------------------------------------------------------
// Kernel 2: flash attention. Warp-local online softmax: each warp owns
// 16 rows x (its 32-key half of every tile), keeps m/l/O(128 cols) private,
// P lives in registers and feeds P@V directly. One barrier per iter.
// ---------------------------------------------------------------------------
#define PQ 136
#define PV 72
#define SM_Q   (BM * PQ)                 // 8704
#define SM_K   (BN * PQ)                 // 8704 per buf
#define SM_VT  (D_HEAD * PV)             // 9216 per buf
#define ATTN_SMEM_FLOATS (SM_Q + 2 * SM_K + 2 * SM_VT)
#define ATTN_SMEM_BYTES  (ATTN_SMEM_FLOATS * 4)

__global__ __launch_bounds__(256, 1) void attn_kernel(float* __restrict__ out)
{
    extern __shared__ float smem[];
    float* sQ   = smem;                  // [64][136]
    float* sK0  = sQ + SM_Q;             // 2x [64][136]
    float* sVt0 = sK0 + 2 * SM_K;        // 2x [128][72]

    const int tid = threadIdx.x, lane = tid & 31, wid = tid >> 5;
    const int rg = (wid & 3) * 16, wc = wid >> 2;
    const int lq = lane >> 2, lr = lane & 3;
    const int q0 = blockIdx.x * BM;

    // Prologue: Q tile + K/V tile 0 (one cp.async group).
    #pragma unroll
    for (int i = 0; i < 8; i++) {
        int c = tid + 256 * i;
        int r = c >> 5, c4 = (c & 31) * 4;
        cp_async16(&sQ[r * PQ + c4], &g_q[(size_t)(q0 + r) * D_HEAD + c4]);
    }
    #pragma unroll
    for (int i = 0; i < 8; i++) {
        int c = tid + 256 * i;
        int r = c >> 5, c4 = (c & 31) * 4;
        cp_async16(&sK0[r * PQ + c4], &g_k[(size_t)r * D_HEAD + c4]);
    }
    #pragma unroll
    for (int i = 0; i < 8; i++) {
        int c = tid + 256 * i;
        int d = c >> 4, c4 = (c & 15) * 4;
        cp_async16(&sVt0[d * PV + c4], &g_vt[(size_t)d * N_TOK + c4]);
    }
    CP_COMMIT();

    float oacc[16][4] = {};
    float m_lo = -INFINITY, m_hi = -INFINITY;
    float l_lo = 0.f, l_hi = 0.f;

    const int NT = N_TOK / BN;
    for (int t = 0; t < NT; t++) {
        float* sK  = sK0  + (t & 1) * SM_K;
        float* sVt = sVt0 + (t & 1) * SM_VT;

        CP_WAIT(0);
        __syncthreads();     // tile t visible to all; all warps done with t-1

        if (t + 1 < NT) {
            float* nK  = sK0  + ((t + 1) & 1) * SM_K;
            float* nVt = sVt0 + ((t + 1) & 1) * SM_VT;
            size_t kg = (size_t)(t + 1) * BN;
            #pragma unroll
            for (int i = 0; i < 8; i++) {
                int c = tid + 256 * i;
                int r = c >> 5, c4 = (c & 31) * 4;
                cp_async16(&nK[r * PQ + c4], &g_k[(kg + r) * D_HEAD + c4]);
            }
            #pragma unroll
            for (int i = 0; i < 8; i++) {
                int c = tid + 256 * i;
                int d = c >> 4, c4 = (c & 15) * 4;
                cp_async16(&nVt[d * PV + c4], &g_vt[(size_t)d * N_TOK + kg + c4]);
            }
            CP_COMMIT();
        }

        // ---- S = Qs @ K^T over this warp's 32-key half ----
        float sacc[4][4] = {};
        #pragma unroll
        for (int ks = 0; ks < 16; ks++) {
            int d0 = ks * 8;
            float2 fa0 = *(const float2*)&sQ[(rg + lq) * PQ + d0 + 2 * lr];
            float2 fa1 = *(const float2*)&sQ[(rg + lq + 8) * PQ + d0 + 2 * lr];
            uint32_t a0 = fu(fa0.x), a1 = fu(fa1.x), a2 = fu(fa0.y), a3 = fu(fa1.y);
            #pragma unroll
            for (int nb = 0; nb < 4; nb++) {
                float2 fb = *(const float2*)&sK[(wc * 32 + nb * 8 + lq) * PQ + d0 + 2 * lr];
                mma_tf32(sacc[nb], a0, a1, a2, a3, fu(fb.x), fu(fb.y));
            }
        }

        // ---- warp-local online softmax (log2 domain) ----
        float tm_lo = -INFINITY, tm_hi = -INFINITY;
        #pragma unroll
        for (int nb = 0; nb < 4; nb++) {
            tm_lo = fmaxf(tm_lo, fmaxf(sacc[nb][0], sacc[nb][1]));
            tm_hi = fmaxf(tm_hi, fmaxf(sacc[nb][2], sacc[nb][3]));
        }
        tm_lo = fmaxf(tm_lo, __shfl_xor_sync(0xffffffffu, tm_lo, 1));
        tm_lo = fmaxf(tm_lo, __shfl_xor_sync(0xffffffffu, tm_lo, 2));
        tm_hi = fmaxf(tm_hi, __shfl_xor_sync(0xffffffffu, tm_hi, 1));
        tm_hi = fmaxf(tm_hi, __shfl_xor_sync(0xffffffffu, tm_hi, 2));

        float mn_lo = fmaxf(m_lo, tm_lo), mn_hi = fmaxf(m_hi, tm_hi);
        float al_lo = ex2(m_lo - mn_lo), al_hi = ex2(m_hi - mn_hi);
        m_lo = mn_lo; m_hi = mn_hi;

        float p[4][4];
        float ps_lo = 0.f, ps_hi = 0.f;
        #pragma unroll
        for (int nb = 0; nb < 4; nb++) {
            p[nb][0] = tf32_rna(ex2(sacc[nb][0] - mn_lo));
            p[nb][1] = tf32_rna(ex2(sacc[nb][1] - mn_lo));
            p[nb][2] = tf32_rna(ex2(sacc[nb][2] - mn_hi));
            p[nb][3] = tf32_rna(ex2(sacc[nb][3] - mn_hi));
            ps_lo += p[nb][0] + p[nb][1];
            ps_hi += p[nb][2] + p[nb][3];
        }
        ps_lo += __shfl_xor_sync(0xffffffffu, ps_lo, 1);
        ps_lo += __shfl_xor_sync(0xffffffffu, ps_lo, 2);
        ps_hi += __shfl_xor_sync(0xffffffffu, ps_hi, 1);
        ps_hi += __shfl_xor_sync(0xffffffffu, ps_hi, 2);
        l_lo = l_lo * al_lo + ps_lo;
        l_hi = l_hi * al_hi + ps_hi;

        #pragma unroll
        for (int nb2 = 0; nb2 < 16; nb2++) {
            oacc[nb2][0] *= al_lo; oacc[nb2][1] *= al_lo;
            oacc[nb2][2] *= al_hi; oacc[nb2][3] *= al_hi;
        }

        // ---- O += P @ V (P from registers; full 128 d-cols) ----
        #pragma unroll
        for (int k2 = 0; k2 < 4; k2++) {
            uint32_t a0 = fu(p[k2][0]), a1 = fu(p[k2][2]);
            uint32_t a2 = fu(p[k2][1]), a3 = fu(p[k2][3]);
            int key0 = wc * 32 + k2 * 8;
            #pragma unroll
            for (int nb2 = 0; nb2 < 16; nb2++) {
                float2 fb = *(const float2*)&sVt[(nb2 * 8 + lq) * PV + key0 + 2 * lr];
                mma_tf32(oacc[nb2], a0, a1, a2, a3, fu(fb.x), fu(fb.y));
            }
        }
    }

    // ---- Epilogue: merge the two key-halves per row group ----
    __syncthreads();
    float* eO = smem;            // [64][136] alias (sQ dead)
    float* eM = sK0;             // [64]
    float* eL = sK0 + 64;        // [64]

    if (wc == 1) {
        if (lr == 0) {
            eM[rg + lq] = m_lo;  eM[rg + lq + 8] = m_hi;
            eL[rg + lq] = l_lo;  eL[rg + lq + 8] = l_hi;
        }
        #pragma unroll
        for (int nb2 = 0; nb2 < 16; nb2++) {
            int c = nb2 * 8 + 2 * lr;
            *(float2*)&eO[(rg + lq) * PQ + c]     = make_float2(oacc[nb2][0], oacc[nb2][1]);
            *(float2*)&eO[(rg + lq + 8) * PQ + c] = make_float2(oacc[nb2][2], oacc[nb2][3]);
        }
    }
    __syncthreads();

    if (wc == 0) {
        float m1lo = eM[rg + lq], m1hi = eM[rg + lq + 8];
        float l1lo = eL[rg + lq], l1hi = eL[rg + lq + 8];
        float Mlo = fmaxf(m_lo, m1lo), Mhi = fmaxf(m_hi, m1hi);
        float s0lo = ex2(m_lo - Mlo), s1lo = ex2(m1lo - Mlo);
        float s0hi = ex2(m_hi - Mhi), s1hi = ex2(m1hi - Mhi);
        float ilo = 1.f / (l_lo * s0lo + l1lo * s1lo);
        float ihi = 1.f / (l_hi * s0hi + l1hi * s1hi);
        #pragma unroll
        for (int nb2 = 0; nb2 < 16; nb2++) {
            int c = nb2 * 8 + 2 * lr;
            float2 o1a = *(const float2*)&eO[(rg + lq) * PQ + c];
            float2 o1b = *(const float2*)&eO[(rg + lq + 8) * PQ + c];
            *(float2*)&out[(size_t)(q0 + rg + lq) * D_HEAD + c] =
                make_float2((oacc[nb2][0] * s0lo + o1a.x * s1lo) * ilo,
                            (oacc[nb2][1] * s0lo + o1a.y * s1lo) * ilo);
            *(float2*)&out[(size_t)(q0 + rg + lq + 8) * D_HEAD + c] =
                make_float2((oacc[nb2][2] * s0hi + o1b.x * s1hi) * ihi,
                            (oacc[nb2][3] * s0hi + o1b.y * s1hi) * ihi);
        }
    }
}

// ---------------------------------------------------------------------------
extern "C" void kernel_launch(void* const* d_in, const int* in_sizes, int n_in,
                              void* d_out, int out_size)
{
    const float* z  = (const float*)d_in[0];
    const float* Wq = (const float*)d_in[1];
    const float* bq = (const float*)d_in[2];
    const float* Wk = (const float*)d_in[3];
    const float* bk = (const float*)d_in[4];
    const float* Wv = (const float*)d_in[5];
    const float* bv = (const float*)d_in[6];
    float* out = (float*)d_out;

    cudaFuncSetAttribute(qkv_kernel, cudaFuncAttributeMaxDynamicSharedMemorySize,
                         QKV_SMEM_BYTES);
    cudaFuncSetAttribute(attn_kernel, cudaFuncAttributeMaxDynamicSharedMemorySize,
                         ATTN_SMEM_BYTES);

    prep_kernel<<<1024, 256>>>(z, Wq, Wk, Wv);

    dim3 gqkv(N_TOK / 128, 3);
    qkv_kernel<<<gqkv, 256, QKV_SMEM_BYTES>>>(bq, bk, bv);

    attn_kernel<<<N_TOK / BM, 256, ATTN_SMEM_BYTES>>>(out);
}

// round 5
// speedup vs baseline: 4.5008x; 1.0569x over previous
#include <cuda_runtime.h>
#include <math.h>
#include <stdint.h>

#define N_TOK  8192
#define IN_DIM 1024
#define D_HEAD 128
#define BM 64
#define BN 64

// Scratch (allocation-free rule).
__device__ float g_q[N_TOK * D_HEAD];    // [n][d_perm], scaled by log2e/sqrt(d), tf32
__device__ float g_k[N_TOK * D_HEAD];    // [n][d_perm], tf32
__device__ float g_vt[D_HEAD * N_TOK];   // [d][key] natural order, tf32
__device__ float g_zr[N_TOK * IN_DIM];   // z tf32, k-permuted within 8-blocks
__device__ float g_wt[3 * IN_DIM * D_HEAD]; // W^T [mat][col][k], tf32, k-permuted

__device__ __forceinline__ float tf32_rna(float x) {
    uint32_t u;
    asm("cvt.rna.tf32.f32 %0, %1;" : "=r"(u) : "f"(x));
    return __uint_as_float(u);
}
__device__ __forceinline__ uint32_t fu(float x) { return __float_as_uint(x); }
__device__ __forceinline__ float ex2(float x) {
    float y;
    asm("ex2.approx.ftz.f32 %0, %1;" : "=f"(y) : "f"(x));
    return y;
}

__device__ __forceinline__ void mma_tf32(float (&d)[4],
    uint32_t a0, uint32_t a1, uint32_t a2, uint32_t a3,
    uint32_t b0, uint32_t b1)
{
    asm volatile(
        "mma.sync.aligned.m16n8k8.row.col.f32.tf32.tf32.f32 "
        "{%0,%1,%2,%3}, {%4,%5,%6,%7}, {%8,%9}, {%0,%1,%2,%3};\n"
        : "+f"(d[0]), "+f"(d[1]), "+f"(d[2]), "+f"(d[3])
        : "r"(a0), "r"(a1), "r"(a2), "r"(a3), "r"(b0), "r"(b1));
}

__device__ __forceinline__ void cp_async16(void* sdst, const void* gsrc) {
    uint32_t s = (uint32_t)__cvta_generic_to_shared(sdst);
    asm volatile("cp.async.cg.shared.global [%0], [%1], 16;\n" :: "r"(s), "l"(gsrc));
}
#define CP_COMMIT() asm volatile("cp.async.commit_group;\n" ::: "memory")
#define CP_WAIT(n)  asm volatile("cp.async.wait_group %0;\n" :: "n"(n) : "memory")

// ---------------------------------------------------------------------------
// Kernel 0: RNA-round to tf32.  z: k-permuted [0,4,1,5,2,6,3,7] per 8-block.
// W: transposed to [col][k] with the same k-permutation.
// ---------------------------------------------------------------------------
__global__ __launch_bounds__(256) void prep_kernel(
    const float* __restrict__ z,
    const float* __restrict__ Wq, const float* __restrict__ Wk,
    const float* __restrict__ Wv)
{
    const int NZ4 = (N_TOK * IN_DIM) / 4;
    const int NWE = IN_DIM * D_HEAD;
    int stride = gridDim.x * blockDim.x;
    int tid0 = blockIdx.x * blockDim.x + threadIdx.x;

    for (int i = tid0; i < NZ4; i += stride) {
        float4 v = ((const float4*)z)[i];
        int base = i * 4;
        int n = base >> 10, k = base & 1023;
        int blk = k & ~7;
        int off = (k & 4) ? 1 : 0;            // second half of 8-block -> odd slots
        float* dst = g_zr + (size_t)n * IN_DIM + blk + off;
        dst[0] = tf32_rna(v.x);
        dst[2] = tf32_rna(v.y);
        dst[4] = tf32_rna(v.z);
        dst[6] = tf32_rna(v.w);
    }
    // W^T with k-perm: read coalesced over columns, scatter writes.
    for (int i = tid0; i < NWE; i += stride) {
        int k = i >> 7, c = i & 127;
        int j = k & 7;
        int kp = (k & ~7) + ((j & 4) ? 2 * (j - 4) + 1 : 2 * j);
        size_t dsti = (size_t)c * IN_DIM + kp;
        g_wt[dsti]               = tf32_rna(Wq[i]);
        g_wt[NWE + dsti]         = tf32_rna(Wk[i]);
        g_wt[2 * (size_t)NWE + dsti] = tf32_rna(Wv[i]);
    }
}

// ---------------------------------------------------------------------------
// Kernel 1: QKV projection, tf32 mma, all fragment loads LDS.64.
// ---------------------------------------------------------------------------
#define QK_KS 32
#define ZP 40            // pitch for z and W^T tiles (conflict-free, 16B-aligned)
#define TP 129
#define QKV_SMEM_FLOATS (4 * 128 * ZP)     // 20480 floats = 80KB
#define QKV_SMEM_BYTES  (QKV_SMEM_FLOATS * 4)

__global__ __launch_bounds__(256) void qkv_kernel(
    const float* __restrict__ bq, const float* __restrict__ bk,
    const float* __restrict__ bv)
{
    extern __shared__ float sm[];
    float* sZ = sm;                   // [2][128][40]
    float* sW = sm + 2 * 128 * ZP;    // [2][128 cols][40]  (W^T tile)

    const int mat = blockIdx.y;
    const float* Wt = g_wt + (size_t)mat * IN_DIM * D_HEAD;
    const float* b = (mat == 0) ? bq : (mat == 1) ? bk : bv;

    const int tid = threadIdx.x, lane = tid & 31, wid = tid >> 5;
    const int rg = (wid & 3) * 32, wc = wid >> 2;
    const int lq = lane >> 2, lr = lane & 3;
    const int row0 = blockIdx.x * 128;

    float acc[2][8][4] = {};

    auto load_tiles = [&](int kt, int buf) {
        float* dZ = sZ + buf * 128 * ZP;
        float* dW = sW + buf * 128 * ZP;
        #pragma unroll
        for (int i = 0; i < 4; i++) {
            int c = tid + 256 * i;
            int r = c >> 3, seg = (c & 7) * 4;
            cp_async16(&dZ[r * ZP + seg],
                       &g_zr[(size_t)(row0 + r) * IN_DIM + kt * QK_KS + seg]);
            cp_async16(&dW[r * ZP + seg],
                       &Wt[(size_t)r * IN_DIM + kt * QK_KS + seg]);
        }
        CP_COMMIT();
    };

    load_tiles(0, 0);
    const int NKT = IN_DIM / QK_KS;
    for (int kt = 0; kt < NKT; kt++) {
        if (kt + 1 < NKT) { load_tiles(kt + 1, (kt + 1) & 1); CP_WAIT(1); }
        else CP_WAIT(0);
        __syncthreads();
        float* cZ = sZ + (kt & 1) * 128 * ZP;
        float* cW = sW + (kt & 1) * 128 * ZP;
        #pragma unroll
        for (int ks = 0; ks < 4; ks++) {
            int d0 = ks * 8;
            uint32_t A[2][4];
            #pragma unroll
            for (int mt = 0; mt < 2; mt++) {
                int r = rg + mt * 16 + lq;
                float2 fa0 = *(const float2*)&cZ[r * ZP + d0 + 2 * lr];
                float2 fa1 = *(const float2*)&cZ[(r + 8) * ZP + d0 + 2 * lr];
                A[mt][0] = fu(fa0.x); A[mt][1] = fu(fa1.x);
                A[mt][2] = fu(fa0.y); A[mt][3] = fu(fa1.y);
            }
            #pragma unroll
            for (int nb = 0; nb < 8; nb++) {
                int ncol = wc * 64 + nb * 8 + lq;
                float2 fb = *(const float2*)&cW[ncol * ZP + d0 + 2 * lr];
                mma_tf32(acc[0][nb], A[0][0], A[0][1], A[0][2], A[0][3], fu(fb.x), fu(fb.y));
                mma_tf32(acc[1][nb], A[1][0], A[1][1], A[1][2], A[1][3], fu(fb.x), fu(fb.y));
            }
        }
        __syncthreads();
    }

    // Epilogue
    const int s_off = (lr < 2) ? 4 * lr : 4 * lr - 7;   // perm slot of col 2lr
    if (mat < 2) {
        float* g = (mat == 0) ? g_q : g_k;
        // log2e / sqrt(128) folded into Q so softmax runs in exp2 domain.
        const float scl = (mat == 0) ? 0.12753785626672556f : 1.0f;
        #pragma unroll
        for (int mt = 0; mt < 2; mt++)
            #pragma unroll
            for (int nb = 0; nb < 8; nb++) {
                int cbase = wc * 64 + nb * 8;
                int c0 = cbase + 2 * lr;
                float b0v = b[c0], b1v = b[c0 + 1];
                int s0 = cbase + s_off;
                size_t r = row0 + rg + mt * 16 + lq;
                g[r * D_HEAD + s0]           = tf32_rna((acc[mt][nb][0] + b0v) * scl);
                g[r * D_HEAD + s0 + 2]       = tf32_rna((acc[mt][nb][1] + b1v) * scl);
                g[(r + 8) * D_HEAD + s0]     = tf32_rna((acc[mt][nb][2] + b0v) * scl);
                g[(r + 8) * D_HEAD + s0 + 2] = tf32_rna((acc[mt][nb][3] + b1v) * scl);
            }
    } else {
        float* sT = sm;   // [128][129] alias (16512 < 20480 floats)
        #pragma unroll
        for (int mt = 0; mt < 2; mt++)
            #pragma unroll
            for (int nb = 0; nb < 8; nb++) {
                int c0 = wc * 64 + nb * 8 + 2 * lr;
                float b0v = b[c0], b1v = b[c0 + 1];
                int r = rg + mt * 16 + lq;
                sT[r * TP + c0]           = tf32_rna(acc[mt][nb][0] + b0v);
                sT[r * TP + c0 + 1]       = tf32_rna(acc[mt][nb][1] + b1v);
                sT[(r + 8) * TP + c0]     = tf32_rna(acc[mt][nb][2] + b0v);
                sT[(r + 8) * TP + c0 + 1] = tf32_rna(acc[mt][nb][3] + b1v);
            }
        __syncthreads();
        #pragma unroll
        for (int i = 0; i < 64; i++) {
            int idx = tid + 256 * i;
            int d = idx >> 7;
            int key = idx & 127;
            g_vt[(size_t)d * N_TOK + row0 + key] = sT[key * TP + d];
        }
    }
}

// ---------------------------------------------------------------------------
// Kernel 2: flash attention. Q fragments hoisted to registers (loop-invariant);
// warp-local online softmax; P in registers; one barrier per iteration.
// ---------------------------------------------------------------------------
#define PQ 136
#define PV 72
#define SM_Q   (BM * PQ)                 // 8704
#define SM_K   (BN * PQ)                 // 8704 per buf
#define SM_VT  (D_HEAD * PV)             // 9216 per buf
#define ATTN_SMEM_FLOATS (SM_Q + 2 * SM_K + 2 * SM_VT)
#define ATTN_SMEM_BYTES  (ATTN_SMEM_FLOATS * 4)

__global__ __launch_bounds__(256, 1) void attn_kernel(float* __restrict__ out)
{
    extern __shared__ float smem[];
    float* sQ   = smem;                  // [64][136]
    float* sK0  = sQ + SM_Q;             // 2x [64][136]
    float* sVt0 = sK0 + 2 * SM_K;        // 2x [128][72]

    const int tid = threadIdx.x, lane = tid & 31, wid = tid >> 5;
    const int rg = (wid & 3) * 16, wc = wid >> 2;
    const int lq = lane >> 2, lr = lane & 3;
    const int q0 = blockIdx.x * BM;

    // Prologue: Q tile + K/V tile 0 (one cp.async group).
    #pragma unroll
    for (int i = 0; i < 8; i++) {
        int c = tid + 256 * i;
        int r = c >> 5, c4 = (c & 31) * 4;
        cp_async16(&sQ[r * PQ + c4], &g_q[(size_t)(q0 + r) * D_HEAD + c4]);
    }
    #pragma unroll
    for (int i = 0; i < 8; i++) {
        int c = tid + 256 * i;
        int r = c >> 5, c4 = (c & 31) * 4;
        cp_async16(&sK0[r * PQ + c4], &g_k[(size_t)r * D_HEAD + c4]);
    }
    #pragma unroll
    for (int i = 0; i < 8; i++) {
        int c = tid + 256 * i;
        int d = c >> 4, c4 = (c & 15) * 4;
        cp_async16(&sVt0[d * PV + c4], &g_vt[(size_t)d * N_TOK + c4]);
    }
    CP_COMMIT();
    CP_WAIT(0);
    __syncthreads();

    // Hoist loop-invariant Q fragments into registers (64 regs).
    uint32_t qa[16][4];
    #pragma unroll
    for (int ks = 0; ks < 16; ks++) {
        int d0 = ks * 8;
        float2 fa0 = *(const float2*)&sQ[(rg + lq) * PQ + d0 + 2 * lr];
        float2 fa1 = *(const float2*)&sQ[(rg + lq + 8) * PQ + d0 + 2 * lr];
        qa[ks][0] = fu(fa0.x); qa[ks][1] = fu(fa1.x);
        qa[ks][2] = fu(fa0.y); qa[ks][3] = fu(fa1.y);
    }

    float oacc[16][4] = {};
    float m_lo = -INFINITY, m_hi = -INFINITY;
    float l_lo = 0.f, l_hi = 0.f;

    const int NT = N_TOK / BN;
    for (int t = 0; t < NT; t++) {
        float* sK  = sK0  + (t & 1) * SM_K;
        float* sVt = sVt0 + (t & 1) * SM_VT;

        // Prefetch tile t+1 into the other buffer (safe: all warps synced past t-1).
        if (t + 1 < NT) {
            float* nK  = sK0  + ((t + 1) & 1) * SM_K;
            float* nVt = sVt0 + ((t + 1) & 1) * SM_VT;
            size_t kg = (size_t)(t + 1) * BN;
            #pragma unroll
            for (int i = 0; i < 8; i++) {
                int c = tid + 256 * i;
                int r = c >> 5, c4 = (c & 31) * 4;
                cp_async16(&nK[r * PQ + c4], &g_k[(kg + r) * D_HEAD + c4]);
            }
            #pragma unroll
            for (int i = 0; i < 8; i++) {
                int c = tid + 256 * i;
                int d = c >> 4, c4 = (c & 15) * 4;
                cp_async16(&nVt[d * PV + c4], &g_vt[(size_t)d * N_TOK + kg + c4]);
            }
            CP_COMMIT();
        }

        // ---- S = Qs @ K^T over this warp's 32-key half ----
        float sacc[4][4] = {};
        #pragma unroll
        for (int ks = 0; ks < 16; ks++) {
            int d0 = ks * 8;
            #pragma unroll
            for (int nb = 0; nb < 4; nb++) {
                float2 fb = *(const float2*)&sK[(wc * 32 + nb * 8 + lq) * PQ + d0 + 2 * lr];
                mma_tf32(sacc[nb], qa[ks][0], qa[ks][1], qa[ks][2], qa[ks][3],
                         fu(fb.x), fu(fb.y));
            }
        }

        // ---- warp-local online softmax (log2 domain) ----
        float tm_lo = -INFINITY, tm_hi = -INFINITY;
        #pragma unroll
        for (int nb = 0; nb < 4; nb++) {
            tm_lo = fmaxf(tm_lo, fmaxf(sacc[nb][0], sacc[nb][1]));
            tm_hi = fmaxf(tm_hi, fmaxf(sacc[nb][2], sacc[nb][3]));
        }
        tm_lo = fmaxf(tm_lo, __shfl_xor_sync(0xffffffffu, tm_lo, 1));
        tm_lo = fmaxf(tm_lo, __shfl_xor_sync(0xffffffffu, tm_lo, 2));
        tm_hi = fmaxf(tm_hi, __shfl_xor_sync(0xffffffffu, tm_hi, 1));
        tm_hi = fmaxf(tm_hi, __shfl_xor_sync(0xffffffffu, tm_hi, 2));

        float mn_lo = fmaxf(m_lo, tm_lo), mn_hi = fmaxf(m_hi, tm_hi);
        float al_lo = ex2(m_lo - mn_lo), al_hi = ex2(m_hi - mn_hi);
        m_lo = mn_lo; m_hi = mn_hi;

        float p[4][4];
        float ps_lo = 0.f, ps_hi = 0.f;
        #pragma unroll
        for (int nb = 0; nb < 4; nb++) {
            p[nb][0] = tf32_rna(ex2(sacc[nb][0] - mn_lo));
            p[nb][1] = tf32_rna(ex2(sacc[nb][1] - mn_lo));
            p[nb][2] = tf32_rna(ex2(sacc[nb][2] - mn_hi));
            p[nb][3] = tf32_rna(ex2(sacc[nb][3] - mn_hi));
            ps_lo += p[nb][0] + p[nb][1];
            ps_hi += p[nb][2] + p[nb][3];
        }
        ps_lo += __shfl_xor_sync(0xffffffffu, ps_lo, 1);
        ps_lo += __shfl_xor_sync(0xffffffffu, ps_lo, 2);
        ps_hi += __shfl_xor_sync(0xffffffffu, ps_hi, 1);
        ps_hi += __shfl_xor_sync(0xffffffffu, ps_hi, 2);
        l_lo = l_lo * al_lo + ps_lo;
        l_hi = l_hi * al_hi + ps_hi;

        #pragma unroll
        for (int nb2 = 0; nb2 < 16; nb2++) {
            oacc[nb2][0] *= al_lo; oacc[nb2][1] *= al_lo;
            oacc[nb2][2] *= al_hi; oacc[nb2][3] *= al_hi;
        }

        // ---- O += P @ V (P from registers; full 128 d-cols) ----
        #pragma unroll
        for (int k2 = 0; k2 < 4; k2++) {
            uint32_t a0 = fu(p[k2][0]), a1 = fu(p[k2][2]);
            uint32_t a2 = fu(p[k2][1]), a3 = fu(p[k2][3]);
            int key0 = wc * 32 + k2 * 8;
            #pragma unroll
            for (int nb2 = 0; nb2 < 16; nb2++) {
                float2 fb = *(const float2*)&sVt[(nb2 * 8 + lq) * PV + key0 + 2 * lr];
                mma_tf32(oacc[nb2], a0, a1, a2, a3, fu(fb.x), fu(fb.y));
            }
        }

        if (t + 1 < NT) {
            CP_WAIT(0);
            __syncthreads();   // tile t+1 visible; all warps done with tile t
        }
    }

    // ---- Epilogue: merge the two key-halves per row group ----
    __syncthreads();
    float* eO = smem;            // [64][136] alias (sQ dead)
    float* eM = sK0;             // [64]
    float* eL = sK0 + 64;        // [64]

    if (wc == 1) {
        if (lr == 0) {
            eM[rg + lq] = m_lo;  eM[rg + lq + 8] = m_hi;
            eL[rg + lq] = l_lo;  eL[rg + lq + 8] = l_hi;
        }
        #pragma unroll
        for (int nb2 = 0; nb2 < 16; nb2++) {
            int c = nb2 * 8 + 2 * lr;
            *(float2*)&eO[(rg + lq) * PQ + c]     = make_float2(oacc[nb2][0], oacc[nb2][1]);
            *(float2*)&eO[(rg + lq + 8) * PQ + c] = make_float2(oacc[nb2][2], oacc[nb2][3]);
        }
    }
    __syncthreads();

    if (wc == 0) {
        float m1lo = eM[rg + lq], m1hi = eM[rg + lq + 8];
        float l1lo = eL[rg + lq], l1hi = eL[rg + lq + 8];
        float Mlo = fmaxf(m_lo, m1lo), Mhi = fmaxf(m_hi, m1hi);
        float s0lo = ex2(m_lo - Mlo), s1lo = ex2(m1lo - Mlo);
        float s0hi = ex2(m_hi - Mhi), s1hi = ex2(m1hi - Mhi);
        float ilo = 1.f / (l_lo * s0lo + l1lo * s1lo);
        float ihi = 1.f / (l_hi * s0hi + l1hi * s1hi);
        #pragma unroll
        for (int nb2 = 0; nb2 < 16; nb2++) {
            int c = nb2 * 8 + 2 * lr;
            float2 o1a = *(const float2*)&eO[(rg + lq) * PQ + c];
            float2 o1b = *(const float2*)&eO[(rg + lq + 8) * PQ + c];
            *(float2*)&out[(size_t)(q0 + rg + lq) * D_HEAD + c] =
                make_float2((oacc[nb2][0] * s0lo + o1a.x * s1lo) * ilo,
                            (oacc[nb2][1] * s0lo + o1a.y * s1lo) * ilo);
            *(float2*)&out[(size_t)(q0 + rg + lq + 8) * D_HEAD + c] =
                make_float2((oacc[nb2][2] * s0hi + o1b.x * s1hi) * ihi,
                            (oacc[nb2][3] * s0hi + o1b.y * s1hi) * ihi);
        }
    }
}

// ---------------------------------------------------------------------------
extern "C" void kernel_launch(void* const* d_in, const int* in_sizes, int n_in,
                              void* d_out, int out_size)
{
    const float* z  = (const float*)d_in[0];
    const float* Wq = (const float*)d_in[1];
    const float* bq = (const float*)d_in[2];
    const float* Wk = (const float*)d_in[3];
    const float* bk = (const float*)d_in[4];
    const float* Wv = (const float*)d_in[5];
    const float* bv = (const float*)d_in[6];
    float* out = (float*)d_out;

    cudaFuncSetAttribute(qkv_kernel, cudaFuncAttributeMaxDynamicSharedMemorySize,
                         QKV_SMEM_BYTES);
    cudaFuncSetAttribute(attn_kernel, cudaFuncAttributeMaxDynamicSharedMemorySize,
                         ATTN_SMEM_BYTES);

    prep_kernel<<<1024, 256>>>(z, Wq, Wk, Wv);

    dim3 gqkv(N_TOK / 128, 3);
    qkv_kernel<<<gqkv, 256, QKV_SMEM_BYTES>>>(bq, bk, bv);

    attn_kernel<<<N_TOK / BM, 256, ATTN_SMEM_BYTES>>>(out);
}

// round 7
// speedup vs baseline: 5.5774x; 1.2392x over previous
#include <cuda_runtime.h>
#include <cuda_fp16.h>
#include <math.h>
#include <stdint.h>

#define N_TOK  8192
#define IN_DIM 1024
#define D_HEAD 128
#define BM 64
#define BN 64

// Scratch (allocation-free rule). All fp16 with fragment-friendly perms.
__device__ __half g_qh[N_TOK * D_HEAD];     // [n][d perm16], scaled log2e/sqrt(d)
__device__ __half g_kh[N_TOK * D_HEAD];     // [n][d perm16]
__device__ __half g_vth[D_HEAD * N_TOK];    // [d][key perm16]
__device__ __half g_zh[N_TOK * IN_DIM];     // z fp16, k perm16
__device__ __half g_wth[3 * IN_DIM * D_HEAD]; // W^T [mat][col][k perm16]

__device__ __forceinline__ float ex2(float x) {
    float y;
    asm("ex2.approx.ftz.f32 %0, %1;" : "=f"(y) : "f"(x));
    return y;
}
__device__ __forceinline__ uint32_t h2u(__half2 h) { return *(uint32_t*)&h; }

// perm within each 16-block: [0,1,8,9,2,3,10,11,4,5,12,13,6,7,14,15]
__device__ __host__ __forceinline__ int slot16(int j) {
    return (j < 8) ? ((j >> 1) * 4 + (j & 1)) : (((j - 8) >> 1) * 4 + 2 + (j & 1));
}

__device__ __forceinline__ void mma_f16(float (&d)[4],
    uint32_t a0, uint32_t a1, uint32_t a2, uint32_t a3,
    uint32_t b0, uint32_t b1)
{
    asm volatile(
        "mma.sync.aligned.m16n8k16.row.col.f32.f16.f16.f32 "
        "{%0,%1,%2,%3}, {%4,%5,%6,%7}, {%8,%9}, {%0,%1,%2,%3};\n"
        : "+f"(d[0]), "+f"(d[1]), "+f"(d[2]), "+f"(d[3])
        : "r"(a0), "r"(a1), "r"(a2), "r"(a3), "r"(b0), "r"(b1));
}

__device__ __forceinline__ void cp_async16(void* sdst, const void* gsrc) {
    uint32_t s = (uint32_t)__cvta_generic_to_shared(sdst);
    asm volatile("cp.async.cg.shared.global [%0], [%1], 16;\n" :: "r"(s), "l"(gsrc));
}
#define CP_COMMIT() asm volatile("cp.async.commit_group;\n" ::: "memory")
#define CP_WAIT(n)  asm volatile("cp.async.wait_group %0;\n" :: "n"(n) : "memory")

// ---------------------------------------------------------------------------
// Kernel 0: round z / W^T to fp16 with k-perm16.
// ---------------------------------------------------------------------------
__global__ __launch_bounds__(256) void prep_kernel(
    const float* __restrict__ z,
    const float* __restrict__ Wq, const float* __restrict__ Wk,
    const float* __restrict__ Wv)
{
    const int NZ4 = (N_TOK * IN_DIM) / 4;
    const int NWE = IN_DIM * D_HEAD;
    int stride = gridDim.x * blockDim.x;
    int tid0 = blockIdx.x * blockDim.x + threadIdx.x;

    for (int i = tid0; i < NZ4; i += stride) {
        float4 v = ((const float4*)z)[i];
        int base = i * 4;
        int n = base >> 10, k = base & 1023;
        int blk = k & ~15, j0 = k & 15;              // j0 in {0,4,8,12}
        __half* dst = g_zh + (size_t)n * IN_DIM + blk;
        *(half2*)&dst[slot16(j0)]     = __floats2half2_rn(v.x, v.y);
        *(half2*)&dst[slot16(j0 + 2)] = __floats2half2_rn(v.z, v.w);
    }
    for (int i = tid0; i < NWE; i += stride) {
        int k = i >> 7, c = i & 127;
        int kp = (k & ~15) + slot16(k & 15);
        size_t dsti = (size_t)c * IN_DIM + kp;
        g_wth[dsti]                  = __float2half_rn(Wq[i]);
        g_wth[NWE + dsti]            = __float2half_rn(Wk[i]);
        g_wth[2 * (size_t)NWE + dsti] = __float2half_rn(Wv[i]);
    }
}

// ---------------------------------------------------------------------------
// Kernel 1: QKV projection, fp16 m16n8k16. Q/K out d-perm16; V out transposed
// with key-perm16.
// ---------------------------------------------------------------------------
#define QK_KS 64          // halves per k-chunk
#define ZPH 72            // tile pitch in halves
#define TPH 130           // V staging pitch in halves
#define QKV_SMEM_BYTES (4 * 128 * ZPH * 2)   // 73728 B

__global__ __launch_bounds__(256) void qkv_kernel(
    const float* __restrict__ bq, const float* __restrict__ bk,
    const float* __restrict__ bv)
{
    extern __shared__ __half qsm[];
    __half* sZ = qsm;                    // [2][128][72]
    __half* sW = qsm + 2 * 128 * ZPH;    // [2][128][72]

    const int mat = blockIdx.y;
    const __half* Wt = g_wth + (size_t)mat * IN_DIM * D_HEAD;
    const float* b = (mat == 0) ? bq : (mat == 1) ? bk : bv;

    const int tid = threadIdx.x, lane = tid & 31, wid = tid >> 5;
    const int rg = (wid & 3) * 32, wc = wid >> 2;
    const int lq = lane >> 2, lr = lane & 3;
    const int row0 = blockIdx.x * 128;

    float acc[2][8][4] = {};

    auto load_tiles = [&](int kt, int buf) {
        __half* dZ = sZ + buf * 128 * ZPH;
        __half* dW = sW + buf * 128 * ZPH;
        #pragma unroll
        for (int i = 0; i < 4; i++) {
            int c = tid + 256 * i;
            int r = c >> 3, seg = (c & 7) * 8;
            cp_async16(&dZ[r * ZPH + seg],
                       &g_zh[(size_t)(row0 + r) * IN_DIM + kt * QK_KS + seg]);
            cp_async16(&dW[r * ZPH + seg],
                       &Wt[(size_t)r * IN_DIM + kt * QK_KS + seg]);
        }
        CP_COMMIT();
    };

    load_tiles(0, 0);
    const int NKT = IN_DIM / QK_KS;   // 16
    for (int kt = 0; kt < NKT; kt++) {
        if (kt + 1 < NKT) { load_tiles(kt + 1, (kt + 1) & 1); CP_WAIT(1); }
        else CP_WAIT(0);
        __syncthreads();
        __half* cZ = sZ + (kt & 1) * 128 * ZPH;
        __half* cW = sW + (kt & 1) * 128 * ZPH;
        #pragma unroll
        for (int ks = 0; ks < 4; ks++) {
            int d0 = ks * 16;
            uint32_t A[2][4];
            #pragma unroll
            for (int mt = 0; mt < 2; mt++) {
                int r = rg + mt * 16 + lq;
                uint2 lo = *(const uint2*)&cZ[r * ZPH + d0 + 4 * lr];
                uint2 hi = *(const uint2*)&cZ[(r + 8) * ZPH + d0 + 4 * lr];
                A[mt][0] = lo.x; A[mt][1] = hi.x; A[mt][2] = lo.y; A[mt][3] = hi.y;
            }
            #pragma unroll
            for (int nb = 0; nb < 8; nb++) {
                int col = wc * 64 + nb * 8 + lq;
                uint2 ub = *(const uint2*)&cW[col * ZPH + d0 + 4 * lr];
                mma_f16(acc[0][nb], A[0][0], A[0][1], A[0][2], A[0][3], ub.x, ub.y);
                mma_f16(acc[1][nb], A[1][0], A[1][1], A[1][2], A[1][3], ub.x, ub.y);
            }
        }
        __syncthreads();
    }

    if (mat < 2) {
        __half* g = (mat == 0) ? g_qh : g_kh;
        const float scl = (mat == 0) ? 0.12753785626672556f : 1.0f; // log2e/sqrt(128)
        #pragma unroll
        for (int mt = 0; mt < 2; mt++)
            #pragma unroll
            for (int nb = 0; nb < 8; nb++) {
                int c0 = wc * 64 + 8 * nb + 2 * lr;            // FIX: + wc*64
                float b0v = b[c0], b1v = b[c0 + 1];
                int blk = wc * 64 + (nb >> 1) * 16;            // FIX: + wc*64
                int s = 4 * lr + 2 * (nb & 1);
                size_t r = row0 + rg + mt * 16 + lq;
                *(half2*)&g[r * D_HEAD + blk + s] =
                    __floats2half2_rn((acc[mt][nb][0] + b0v) * scl,
                                      (acc[mt][nb][1] + b1v) * scl);
                *(half2*)&g[(r + 8) * D_HEAD + blk + s] =
                    __floats2half2_rn((acc[mt][nb][2] + b0v) * scl,
                                      (acc[mt][nb][3] + b1v) * scl);
            }
    } else {
        __half* sT = qsm;    // [128][130] alias (33,280 B < 73,728 B)
        #pragma unroll
        for (int mt = 0; mt < 2; mt++)
            #pragma unroll
            for (int nb = 0; nb < 8; nb++) {
                int c0 = wc * 64 + 8 * nb + 2 * lr;            // FIX: + wc*64
                float b0v = b[c0], b1v = b[c0 + 1];
                int r = rg + mt * 16 + lq;
                *(half2*)&sT[r * TPH + c0] =
                    __floats2half2_rn(acc[mt][nb][0] + b0v, acc[mt][nb][1] + b1v);
                *(half2*)&sT[(r + 8) * TPH + c0] =
                    __floats2half2_rn(acc[mt][nb][2] + b0v, acc[mt][nb][3] + b1v);
            }
        __syncthreads();
        // Transpose + key-perm16 into g_vth [d][key].
        #pragma unroll
        for (int i = 0; i < 32; i++) {
            int idx = tid + 256 * i;           // over 128 d x 64 key-pairs
            int d = idx >> 6, tp = idx & 63;
            int block = tp >> 3, tq = tp & 7;
            int a = tq >> 1, bs = tq & 1;
            int k0 = 16 * block + 2 * a + 8 * bs;
            __half h0 = sT[k0 * TPH + d];
            __half h1 = sT[(k0 + 1) * TPH + d];
            *(half2*)&g_vth[(size_t)d * N_TOK + row0 + 16 * block + 4 * a + 2 * bs] =
                __halves2half2(h0, h1);
        }
    }
}

// ---------------------------------------------------------------------------
// Kernel 2: flash attention, fp16 m16n8k16. Q frags hoisted; warp-local
// online softmax (log2 domain); P packed to half2 in registers.
// ---------------------------------------------------------------------------
#define PQH 136
#define PVH 72
#define SM_QH (BM * PQH)                 // 8704 halves
#define SM_KH (BN * PQH)                 // 8704 per buf
#define SM_VH (D_HEAD * PVH)             // 9216 per buf
#define ATTN_SMEM_HALVES (SM_QH + 2 * SM_KH + 2 * SM_VH)   // 44544
#define ATTN_SMEM_BYTES  (ATTN_SMEM_HALVES * 2)            // 89088 B

__global__ __launch_bounds__(256, 1) void attn_kernel(float* __restrict__ out)
{
    extern __shared__ __half smh[];
    __half* sQ   = smh;
    __half* sK0  = sQ + SM_QH;
    __half* sVt0 = sK0 + 2 * SM_KH;

    const int tid = threadIdx.x, lane = tid & 31, wid = tid >> 5;
    const int rg = (wid & 3) * 16, wc = wid >> 2;
    const int lq = lane >> 2, lr = lane & 3;
    const int q0 = blockIdx.x * BM;

    // Prologue: Q + K/V tile 0.
    #pragma unroll
    for (int i = 0; i < 4; i++) {
        int c = tid + 256 * i;
        int r = c >> 4, seg = (c & 15) * 8;
        cp_async16(&sQ[r * PQH + seg], &g_qh[(size_t)(q0 + r) * D_HEAD + seg]);
    }
    #pragma unroll
    for (int i = 0; i < 4; i++) {
        int c = tid + 256 * i;
        int r = c >> 4, seg = (c & 15) * 8;
        cp_async16(&sK0[r * PQH + seg], &g_kh[(size_t)r * D_HEAD + seg]);
    }
    #pragma unroll
    for (int i = 0; i < 4; i++) {
        int c = tid + 256 * i;
        int d = c >> 3, seg = (c & 7) * 8;
        cp_async16(&sVt0[d * PVH + seg], &g_vth[(size_t)d * N_TOK + seg]);
    }
    CP_COMMIT();
    CP_WAIT(0);
    __syncthreads();

    // Hoist Q fragments (8 k16 steps x 4 regs = 32 regs).
    uint32_t qa[8][4];
    #pragma unroll
    for (int ks = 0; ks < 8; ks++) {
        int d0 = ks * 16;
        uint2 lo = *(const uint2*)&sQ[(rg + lq) * PQH + d0 + 4 * lr];
        uint2 hi = *(const uint2*)&sQ[(rg + lq + 8) * PQH + d0 + 4 * lr];
        qa[ks][0] = lo.x; qa[ks][1] = hi.x; qa[ks][2] = lo.y; qa[ks][3] = hi.y;
    }

    float oacc[16][4] = {};
    float m_lo = -INFINITY, m_hi = -INFINITY;
    float l_lo = 0.f, l_hi = 0.f;

    const int NT = N_TOK / BN;
    for (int t = 0; t < NT; t++) {
        __half* sK  = sK0  + (t & 1) * SM_KH;
        __half* sVt = sVt0 + (t & 1) * SM_VH;

        if (t + 1 < NT) {
            __half* nK  = sK0  + ((t + 1) & 1) * SM_KH;
            __half* nVt = sVt0 + ((t + 1) & 1) * SM_VH;
            size_t kg = (size_t)(t + 1) * BN;
            #pragma unroll
            for (int i = 0; i < 4; i++) {
                int c = tid + 256 * i;
                int r = c >> 4, seg = (c & 15) * 8;
                cp_async16(&nK[r * PQH + seg], &g_kh[(kg + r) * D_HEAD + seg]);
            }
            #pragma unroll
            for (int i = 0; i < 4; i++) {
                int c = tid + 256 * i;
                int d = c >> 3, seg = (c & 7) * 8;
                cp_async16(&nVt[d * PVH + seg], &g_vth[(size_t)d * N_TOK + kg + seg]);
            }
            CP_COMMIT();
        }

        // ---- S = Qs @ K^T over this warp's 32-key half ----
        float sacc[4][4] = {};
        #pragma unroll
        for (int ks = 0; ks < 8; ks++) {
            int d0 = ks * 16;
            #pragma unroll
            for (int nb = 0; nb < 4; nb++) {
                uint2 ub = *(const uint2*)&sK[(wc * 32 + nb * 8 + lq) * PQH + d0 + 4 * lr];
                mma_f16(sacc[nb], qa[ks][0], qa[ks][1], qa[ks][2], qa[ks][3],
                        ub.x, ub.y);
            }
        }

        // ---- warp-local online softmax ----
        float tm_lo = -INFINITY, tm_hi = -INFINITY;
        #pragma unroll
        for (int nb = 0; nb < 4; nb++) {
            tm_lo = fmaxf(tm_lo, fmaxf(sacc[nb][0], sacc[nb][1]));
            tm_hi = fmaxf(tm_hi, fmaxf(sacc[nb][2], sacc[nb][3]));
        }
        tm_lo = fmaxf(tm_lo, __shfl_xor_sync(0xffffffffu, tm_lo, 1));
        tm_lo = fmaxf(tm_lo, __shfl_xor_sync(0xffffffffu, tm_lo, 2));
        tm_hi = fmaxf(tm_hi, __shfl_xor_sync(0xffffffffu, tm_hi, 1));
        tm_hi = fmaxf(tm_hi, __shfl_xor_sync(0xffffffffu, tm_hi, 2));

        float mn_lo = fmaxf(m_lo, tm_lo), mn_hi = fmaxf(m_hi, tm_hi);
        float al_lo = ex2(m_lo - mn_lo), al_hi = ex2(m_hi - mn_hi);
        m_lo = mn_lo; m_hi = mn_hi;

        uint32_t pa[4], pb[4];
        float ps_lo = 0.f, ps_hi = 0.f;
        #pragma unroll
        for (int nb = 0; nb < 4; nb++) {
            __half2 hA = __floats2half2_rn(ex2(sacc[nb][0] - mn_lo),
                                           ex2(sacc[nb][1] - mn_lo));
            __half2 hB = __floats2half2_rn(ex2(sacc[nb][2] - mn_hi),
                                           ex2(sacc[nb][3] - mn_hi));
            float2 fA = __half22float2(hA);
            float2 fB = __half22float2(hB);
            ps_lo += fA.x + fA.y;
            ps_hi += fB.x + fB.y;
            pa[nb] = h2u(hA); pb[nb] = h2u(hB);
        }
        ps_lo += __shfl_xor_sync(0xffffffffu, ps_lo, 1);
        ps_lo += __shfl_xor_sync(0xffffffffu, ps_lo, 2);
        ps_hi += __shfl_xor_sync(0xffffffffu, ps_hi, 1);
        ps_hi += __shfl_xor_sync(0xffffffffu, ps_hi, 2);
        l_lo = l_lo * al_lo + ps_lo;
        l_hi = l_hi * al_hi + ps_hi;

        #pragma unroll
        for (int nb2 = 0; nb2 < 16; nb2++) {
            oacc[nb2][0] *= al_lo; oacc[nb2][1] *= al_lo;
            oacc[nb2][2] *= al_hi; oacc[nb2][3] *= al_hi;
        }

        // ---- O += P @ V ----
        #pragma unroll
        for (int k2 = 0; k2 < 2; k2++) {
            uint32_t a0 = pa[2 * k2], a1 = pb[2 * k2];
            uint32_t a2 = pa[2 * k2 + 1], a3 = pb[2 * k2 + 1];
            int kbase = wc * 32 + 16 * k2;
            #pragma unroll
            for (int nb2 = 0; nb2 < 16; nb2++) {
                uint2 ub = *(const uint2*)&sVt[(nb2 * 8 + lq) * PVH + kbase + 4 * lr];
                mma_f16(oacc[nb2], a0, a1, a2, a3, ub.x, ub.y);
            }
        }

        if (t + 1 < NT) {
            CP_WAIT(0);
            __syncthreads();
        }
    }

    // ---- Epilogue: merge the two key-halves ----
    __syncthreads();
    float* eO = (float*)smh;       // [64][136] floats (alias; loop smem dead)
    float* eM = eO + 64 * PQH;
    float* eL = eM + 64;

    if (wc == 1) {
        if (lr == 0) {
            eM[rg + lq] = m_lo;  eM[rg + lq + 8] = m_hi;
            eL[rg + lq] = l_lo;  eL[rg + lq + 8] = l_hi;
        }
        #pragma unroll
        for (int nb2 = 0; nb2 < 16; nb2++) {
            int c = nb2 * 8 + 2 * lr;
            *(float2*)&eO[(rg + lq) * PQH + c]     = make_float2(oacc[nb2][0], oacc[nb2][1]);
            *(float2*)&eO[(rg + lq + 8) * PQH + c] = make_float2(oacc[nb2][2], oacc[nb2][3]);
        }
    }
    __syncthreads();

    if (wc == 0) {
        float m1lo = eM[rg + lq], m1hi = eM[rg + lq + 8];
        float l1lo = eL[rg + lq], l1hi = eL[rg + lq + 8];
        float Mlo = fmaxf(m_lo, m1lo), Mhi = fmaxf(m_hi, m1hi);
        float s0lo = ex2(m_lo - Mlo), s1lo = ex2(m1lo - Mlo);
        float s0hi = ex2(m_hi - Mhi), s1hi = ex2(m1hi - Mhi);
        float ilo = 1.f / (l_lo * s0lo + l1lo * s1lo);
        float ihi = 1.f / (l_hi * s0hi + l1hi * s1hi);
        #pragma unroll
        for (int nb2 = 0; nb2 < 16; nb2++) {
            int c = nb2 * 8 + 2 * lr;
            float2 o1a = *(const float2*)&eO[(rg + lq) * PQH + c];
            float2 o1b = *(const float2*)&eO[(rg + lq + 8) * PQH + c];
            *(float2*)&out[(size_t)(q0 + rg + lq) * D_HEAD + c] =
                make_float2((oacc[nb2][0] * s0lo + o1a.x * s1lo) * ilo,
                            (oacc[nb2][1] * s0lo + o1a.y * s1lo) * ilo);
            *(float2*)&out[(size_t)(q0 + rg + lq + 8) * D_HEAD + c] =
                make_float2((oacc[nb2][2] * s0hi + o1b.x * s1hi) * ihi,
                            (oacc[nb2][3] * s0hi + o1b.y * s1hi) * ihi);
        }
    }
}

// ---------------------------------------------------------------------------
extern "C" void kernel_launch(void* const* d_in, const int* in_sizes, int n_in,
                              void* d_out, int out_size)
{
    const float* z  = (const float*)d_in[0];
    const float* Wq = (const float*)d_in[1];
    const float* bq = (const float*)d_in[2];
    const float* Wk = (const float*)d_in[3];
    const float* bk = (const float*)d_in[4];
    const float* Wv = (const float*)d_in[5];
    const float* bv = (const float*)d_in[6];
    float* out = (float*)d_out;

    cudaFuncSetAttribute(qkv_kernel, cudaFuncAttributeMaxDynamicSharedMemorySize,
                         QKV_SMEM_BYTES);
    cudaFuncSetAttribute(attn_kernel, cudaFuncAttributeMaxDynamicSharedMemorySize,
                         ATTN_SMEM_BYTES);

    prep_kernel<<<1024, 256>>>(z, Wq, Wk, Wv);

    dim3 gqkv(N_TOK / 128, 3);
    qkv_kernel<<<gqkv, 256, QKV_SMEM_BYTES>>>(bq, bk, bv);

    attn_kernel<<<N_TOK / BM, 256, ATTN_SMEM_BYTES>>>(out);
}